// round 1
// baseline (speedup 1.0000x reference)
#include <cuda_runtime.h>
#include <cstdint>

// Problem constants (checked against in_sizes at launch)
constexpr int MAXN = 100000;
constexpr int C128 = 128;

// Scratch (allocation-free rule: __device__ globals)
__device__ float g_bufA[(size_t)MAXN * C128];  // GEMM output h
__device__ float g_bufB[(size_t)MAXN * C128];  // aggregation output
__device__ float g_dis[MAXN];                  // deg^{-1/2}
__device__ int   g_deg[MAXN];

// ---------------------------------------------------------------------------
// degree / norm
// ---------------------------------------------------------------------------
__global__ void k_deg_init(int n) {
    int i = blockIdx.x * blockDim.x + threadIdx.x;
    if (i < n) g_deg[i] = 1;  // self-loop
}

__global__ void k_deg_count(const int* __restrict__ dst, int e) {
    int i = blockIdx.x * blockDim.x + threadIdx.x;
    if (i < e) atomicAdd(&g_deg[dst[i]], 1);
}

__global__ void k_dis(int n) {
    int i = blockIdx.x * blockDim.x + threadIdx.x;
    if (i < n) g_dis[i] = rsqrtf((float)g_deg[i]);
}

// ---------------------------------------------------------------------------
// Tiled GEMM: h[n, COUT] = relu?(x)[n, CIN] @ W[CIN, COUT]
// Block: 256 threads, tile 64 rows x COUT cols. W fully staged in SMEM.
// ---------------------------------------------------------------------------
template <int CIN, int COUT, bool RELU>
__global__ __launch_bounds__(256) void k_gemm(const float* __restrict__ x,
                                              const float* __restrict__ W,
                                              float* __restrict__ h, int n) {
    extern __shared__ float sm[];
    float4* ws4 = (float4*)sm;                 // [CIN][COUT/4]
    float*  xs  = sm + CIN * COUT;             // [64][CIN]
    float4* xs4 = (float4*)xs;

    const float4* W4 = (const float4*)W;
    const float4* x4 = (const float4*)x;
    const int m0 = blockIdx.x * 64;

    for (int i = threadIdx.x; i < CIN * COUT / 4; i += 256) ws4[i] = W4[i];

    for (int i = threadIdx.x; i < 64 * CIN / 4; i += 256) {
        int r = i / (CIN / 4), c = i % (CIN / 4);
        int m = m0 + r;
        float4 v = make_float4(0.f, 0.f, 0.f, 0.f);
        if (m < n) {
            v = x4[(size_t)m * (CIN / 4) + c];
            if (RELU) {
                v.x = fmaxf(v.x, 0.f); v.y = fmaxf(v.y, 0.f);
                v.z = fmaxf(v.z, 0.f); v.w = fmaxf(v.w, 0.f);
            }
        }
        xs4[i] = v;
    }
    __syncthreads();

    constexpr int TCOLS = COUT / 4;     // 32 (C=128) or 16 (C=64)
    constexpr int TROWS = 256 / TCOLS;  // 8 or 16
    constexpr int RT    = 64 / TROWS;   // 8 or 4
    const int tx = threadIdx.x % TCOLS;
    const int ty = threadIdx.x / TCOLS;

    float4 acc[RT];
#pragma unroll
    for (int r = 0; r < RT; r++) acc[r] = make_float4(0.f, 0.f, 0.f, 0.f);

#pragma unroll 4
    for (int k = 0; k < CIN; k++) {
        float4 wv = ws4[k * TCOLS + tx];
#pragma unroll
        for (int r = 0; r < RT; r++) {
            float xv = xs[(ty * RT + r) * CIN + k];
            acc[r].x = fmaf(xv, wv.x, acc[r].x);
            acc[r].y = fmaf(xv, wv.y, acc[r].y);
            acc[r].z = fmaf(xv, wv.z, acc[r].z);
            acc[r].w = fmaf(xv, wv.w, acc[r].w);
        }
    }

    float4* h4 = (float4*)h;
#pragma unroll
    for (int r = 0; r < RT; r++) {
        int m = m0 + ty * RT + r;
        if (m < n) h4[(size_t)m * TCOLS + tx] = acc[r];
    }
}

// ---------------------------------------------------------------------------
// out[i,:] = b + dis[i]^2 * h[i,:]  (bias + self-loop message, full overwrite)
// ---------------------------------------------------------------------------
template <int C>
__global__ void k_init(const float* __restrict__ h, const float* __restrict__ b,
                       float* __restrict__ out, int n) {
    int i = blockIdx.x * blockDim.x + threadIdx.x;
    constexpr int C4 = C / 4;
    if (i >= n * C4) return;
    int node = i / C4, c4 = i % C4;
    float d = g_dis[node];
    float s = d * d;
    float4 hv = ((const float4*)h)[i];
    float4 bv = ((const float4*)b)[c4];
    float4 o;
    o.x = fmaf(s, hv.x, bv.x); o.y = fmaf(s, hv.y, bv.y);
    o.z = fmaf(s, hv.z, bv.z); o.w = fmaf(s, hv.w, bv.w);
    ((float4*)out)[i] = o;
}

// ---------------------------------------------------------------------------
// Edge scatter: out[dst] += norm * h[src]. Warp per edge, vectorized RED.
// ---------------------------------------------------------------------------
__device__ __forceinline__ void red_add_v4(float* addr, float4 v) {
    asm volatile("red.global.add.v4.f32 [%0], {%1,%2,%3,%4};"
                 :: "l"(addr), "f"(v.x), "f"(v.y), "f"(v.z), "f"(v.w)
                 : "memory");
}
__device__ __forceinline__ void red_add_v2(float* addr, float2 v) {
    asm volatile("red.global.add.v2.f32 [%0], {%1,%2};"
                 :: "l"(addr), "f"(v.x), "f"(v.y)
                 : "memory");
}

template <int C>
__global__ void k_scatter(const float* __restrict__ h,
                          const int* __restrict__ src,
                          const int* __restrict__ dst,
                          float* __restrict__ out, int E) {
    int t = blockIdx.x * blockDim.x + threadIdx.x;
    int w = t >> 5, lane = t & 31;
    if (w >= E) return;
    int s = __ldg(src + w);
    int d = __ldg(dst + w);
    float nrm = g_dis[s] * g_dis[d];
    if (C == 128) {
        float4 v = ((const float4*)h)[(size_t)s * 32 + lane];
        v.x *= nrm; v.y *= nrm; v.z *= nrm; v.w *= nrm;
        red_add_v4(out + (size_t)d * 128 + lane * 4, v);
    } else {  // C == 64
        float2 v = ((const float2*)h)[(size_t)s * 32 + lane];
        v.x *= nrm; v.y *= nrm;
        red_add_v2(out + (size_t)d * 64 + lane * 2, v);
    }
}

// ---------------------------------------------------------------------------
// Launch
// ---------------------------------------------------------------------------
extern "C" void kernel_launch(void* const* d_in, const int* in_sizes, int n_in,
                              void* d_out, int out_size) {
    const float* x  = (const float*)d_in[0];
    const int*   ei = (const int*)d_in[1];
    const float* W1 = (const float*)d_in[2];
    const float* b1 = (const float*)d_in[3];
    const float* W2 = (const float*)d_in[4];
    const float* b2 = (const float*)d_in[5];
    const float* W3 = (const float*)d_in[6];
    const float* b3 = (const float*)d_in[7];
    float* out = (float*)d_out;

    const int n = in_sizes[0] / 128;
    const int E = in_sizes[1] / 2;
    const int* src = ei;
    const int* dst = ei + E;

    float* bufA; float* bufB;
    cudaGetSymbolAddress((void**)&bufA, g_bufA);
    cudaGetSymbolAddress((void**)&bufB, g_bufB);

    const size_t sm128 = (size_t)(128 * 128 + 64 * 128) * sizeof(float);  // 96 KB
    const size_t sm64  = (size_t)(128 * 64 + 64 * 128) * sizeof(float);   // 64 KB
    cudaFuncSetAttribute(k_gemm<128, 128, false>,
                         cudaFuncAttributeMaxDynamicSharedMemorySize, (int)sm128);
    cudaFuncSetAttribute(k_gemm<128, 128, true>,
                         cudaFuncAttributeMaxDynamicSharedMemorySize, (int)sm128);
    cudaFuncSetAttribute(k_gemm<128, 64, true>,
                         cudaFuncAttributeMaxDynamicSharedMemorySize, (int)sm64);

    const int TB = 256;
    const int gN   = (n + TB - 1) / TB;
    const int gE   = (E + TB - 1) / TB;
    const int gM   = (n + 63) / 64;
    const int gSc  = (int)(((long long)E * 32 + TB - 1) / TB);
    const int gI128 = (int)(((long long)n * 32 + TB - 1) / TB);
    const int gI64  = (int)(((long long)n * 16 + TB - 1) / TB);

    // normalization
    k_deg_init<<<gN, TB>>>(n);
    k_deg_count<<<gE, TB>>>(dst, E);
    k_dis<<<gN, TB>>>(n);

    // layer 1: h = x@W1 ; agg = b1 + dis^2*h + scatter
    k_gemm<128, 128, false><<<gM, TB, sm128>>>(x, W1, bufA, n);
    k_init<128><<<gI128, TB>>>(bufA, b1, bufB, n);
    k_scatter<128><<<gSc, TB>>>(bufA, src, dst, bufB, E);

    // layer 2: h = relu(agg)@W2 ; ...
    k_gemm<128, 128, true><<<gM, TB, sm128>>>(bufB, W2, bufA, n);
    k_init<128><<<gI128, TB>>>(bufA, b2, bufB, n);
    k_scatter<128><<<gSc, TB>>>(bufA, src, dst, bufB, E);

    // layer 3: h = relu(agg)@W3 (64 ch) ; write d_out
    k_gemm<128, 64, true><<<gM, TB, sm64>>>(bufB, W3, bufA, n);
    k_init<64><<<gI64, TB>>>(bufA, b3, out, n);
    k_scatter<64><<<gSc, TB>>>(bufA, src, dst, out, E);
}

// round 2
// speedup vs baseline: 1.7488x; 1.7488x over previous
#include <cuda_runtime.h>
#include <cstdint>

constexpr int MAXN = 100000;
constexpr int MAXE = 1600000;
constexpr int C128 = 128;

// Scratch (__device__ globals; allocation-free rule)
__device__ float g_bufA[(size_t)MAXN * C128];  // GEMM output h
__device__ float g_bufB[(size_t)MAXN * C128];  // aggregation output
__device__ float g_dis[MAXN];                  // deg^{-1/2}
__device__ int   g_deg[MAXN];                  // 1 + in-degree
__device__ int   g_rowoff[MAXN];               // CSR exclusive offsets
__device__ int   g_cur[MAXN];                  // fill cursors
__device__ int   g_chunksum[128];
__device__ int   g_chunkoff[128];
__device__ int2  g_csr[MAXE];                  // {src, norm as int bits}

// ---------------------------------------------------------------------------
// degree / norm
// ---------------------------------------------------------------------------
__global__ void k_deg_init(int n) {
    int i = blockIdx.x * blockDim.x + threadIdx.x;
    if (i < n) g_deg[i] = 1;  // self-loop
}
__global__ void k_deg_count(const int* __restrict__ dst, int e) {
    int i = blockIdx.x * blockDim.x + threadIdx.x;
    if (i < e) atomicAdd(&g_deg[dst[i]], 1);
}
__global__ void k_dis(int n) {
    int i = blockIdx.x * blockDim.x + threadIdx.x;
    if (i < n) g_dis[i] = rsqrtf((float)g_deg[i]);
}

// ---------------------------------------------------------------------------
// 2-level exclusive scan of rowlen = deg-1  ->  g_rowoff, g_cur
// ---------------------------------------------------------------------------
__global__ __launch_bounds__(1024) void k_scan_chunk(int n) {
    __shared__ int sm[1024];
    int gid = blockIdx.x * 1024 + threadIdx.x;
    int v = (gid < n) ? (g_deg[gid] - 1) : 0;
    sm[threadIdx.x] = v;
    __syncthreads();
#pragma unroll
    for (int off = 1; off < 1024; off <<= 1) {
        int t = (threadIdx.x >= off) ? sm[threadIdx.x - off] : 0;
        __syncthreads();
        sm[threadIdx.x] += t;
        __syncthreads();
    }
    if (gid < n) g_rowoff[gid] = sm[threadIdx.x] - v;  // exclusive
    if (threadIdx.x == 1023) g_chunksum[blockIdx.x] = sm[1023];
}

__global__ void k_scan_top(int nch) {
    __shared__ int sm[128];
    int v = (threadIdx.x < nch) ? g_chunksum[threadIdx.x] : 0;
    sm[threadIdx.x] = v;
    __syncthreads();
#pragma unroll
    for (int off = 1; off < 128; off <<= 1) {
        int t = (threadIdx.x >= off) ? sm[threadIdx.x - off] : 0;
        __syncthreads();
        sm[threadIdx.x] += t;
        __syncthreads();
    }
    if (threadIdx.x < nch) g_chunkoff[threadIdx.x] = sm[threadIdx.x] - v;
}

__global__ void k_scan_add(int n) {
    int i = blockIdx.x * blockDim.x + threadIdx.x;
    if (i < n) {
        int o = g_rowoff[i] + g_chunkoff[i >> 10];
        g_rowoff[i] = o;
        g_cur[i] = o;
    }
}

__global__ void k_csr_fill(const int* __restrict__ src,
                           const int* __restrict__ dst, int E) {
    int e = blockIdx.x * blockDim.x + threadIdx.x;
    if (e < E) {
        int s = src[e], d = dst[e];
        int pos = atomicAdd(&g_cur[d], 1);
        float nrm = g_dis[s] * g_dis[d];
        g_csr[pos] = make_int2(s, __float_as_int(nrm));
    }
}

// ---------------------------------------------------------------------------
// Tiled GEMM: h[n, COUT] = relu?(x)[n, CIN] @ W[CIN, COUT]
// ---------------------------------------------------------------------------
template <int CIN, int COUT, bool RELU>
__global__ __launch_bounds__(256) void k_gemm(const float* __restrict__ x,
                                              const float* __restrict__ W,
                                              float* __restrict__ h, int n) {
    extern __shared__ float sm[];
    float4* ws4 = (float4*)sm;                 // [CIN][COUT/4]
    float*  xs  = sm + CIN * COUT;             // [64][CIN]
    float4* xs4 = (float4*)xs;

    const float4* W4 = (const float4*)W;
    const float4* x4 = (const float4*)x;
    const int m0 = blockIdx.x * 64;

    for (int i = threadIdx.x; i < CIN * COUT / 4; i += 256) ws4[i] = W4[i];

    for (int i = threadIdx.x; i < 64 * CIN / 4; i += 256) {
        int r = i / (CIN / 4), c = i % (CIN / 4);
        int m = m0 + r;
        float4 v = make_float4(0.f, 0.f, 0.f, 0.f);
        if (m < n) {
            v = x4[(size_t)m * (CIN / 4) + c];
            if (RELU) {
                v.x = fmaxf(v.x, 0.f); v.y = fmaxf(v.y, 0.f);
                v.z = fmaxf(v.z, 0.f); v.w = fmaxf(v.w, 0.f);
            }
        }
        xs4[i] = v;
    }
    __syncthreads();

    constexpr int TCOLS = COUT / 4;
    constexpr int TROWS = 256 / TCOLS;
    constexpr int RT    = 64 / TROWS;
    const int tx = threadIdx.x % TCOLS;
    const int ty = threadIdx.x / TCOLS;

    float4 acc[RT];
#pragma unroll
    for (int r = 0; r < RT; r++) acc[r] = make_float4(0.f, 0.f, 0.f, 0.f);

#pragma unroll 4
    for (int k = 0; k < CIN; k++) {
        float4 wv = ws4[k * TCOLS + tx];
#pragma unroll
        for (int r = 0; r < RT; r++) {
            float xv = xs[(ty * RT + r) * CIN + k];
            acc[r].x = fmaf(xv, wv.x, acc[r].x);
            acc[r].y = fmaf(xv, wv.y, acc[r].y);
            acc[r].z = fmaf(xv, wv.z, acc[r].z);
            acc[r].w = fmaf(xv, wv.w, acc[r].w);
        }
    }

    float4* h4 = (float4*)h;
#pragma unroll
    for (int r = 0; r < RT; r++) {
        int m = m0 + ty * RT + r;
        if (m < n) h4[(size_t)m * TCOLS + tx] = acc[r];
    }
}

// ---------------------------------------------------------------------------
// CSR gather-aggregate (fuses bias + self-loop + neighbor sum):
// out[i,:] = b + dis[i]^2*h[i,:] + sum_e norm[e]*h[src[e],:]
// Warp per node, lane owns C/32 channels.
// ---------------------------------------------------------------------------
template <int C>
__global__ __launch_bounds__(256) void k_aggr(const float* __restrict__ h,
                                              const float* __restrict__ b,
                                              float* __restrict__ out, int n) {
    int i = (blockIdx.x * 256 + threadIdx.x) >> 5;
    int lane = threadIdx.x & 31;
    if (i >= n) return;

    float d = g_dis[i];
    float s2 = d * d;
    int e   = g_rowoff[i];
    int end = e + (g_deg[i] - 1);

    if (C == 128) {
        float4 acc = ((const float4*)b)[lane];
        float4 hv  = ((const float4*)h)[(size_t)i * 32 + lane];
        acc.x = fmaf(s2, hv.x, acc.x); acc.y = fmaf(s2, hv.y, acc.y);
        acc.z = fmaf(s2, hv.z, acc.z); acc.w = fmaf(s2, hv.w, acc.w);

        int2 ed = (e < end) ? __ldg(&g_csr[e]) : make_int2(0, 0);
        while (e < end) {
            int2 nxt = (e + 1 < end) ? __ldg(&g_csr[e + 1]) : ed;
            float nr = __int_as_float(ed.y);
            float4 v = ((const float4*)h)[(size_t)ed.x * 32 + lane];
            acc.x = fmaf(nr, v.x, acc.x); acc.y = fmaf(nr, v.y, acc.y);
            acc.z = fmaf(nr, v.z, acc.z); acc.w = fmaf(nr, v.w, acc.w);
            ed = nxt; e++;
        }
        ((float4*)out)[(size_t)i * 32 + lane] = acc;
    } else {  // C == 64
        float2 acc = ((const float2*)b)[lane];
        float2 hv  = ((const float2*)h)[(size_t)i * 32 + lane];
        acc.x = fmaf(s2, hv.x, acc.x); acc.y = fmaf(s2, hv.y, acc.y);

        int2 ed = (e < end) ? __ldg(&g_csr[e]) : make_int2(0, 0);
        while (e < end) {
            int2 nxt = (e + 1 < end) ? __ldg(&g_csr[e + 1]) : ed;
            float nr = __int_as_float(ed.y);
            float2 v = ((const float2*)h)[(size_t)ed.x * 32 + lane];
            acc.x = fmaf(nr, v.x, acc.x); acc.y = fmaf(nr, v.y, acc.y);
            ed = nxt; e++;
        }
        ((float2*)out)[(size_t)i * 32 + lane] = acc;
    }
}

// ---------------------------------------------------------------------------
// Launch
// ---------------------------------------------------------------------------
extern "C" void kernel_launch(void* const* d_in, const int* in_sizes, int n_in,
                              void* d_out, int out_size) {
    const float* x  = (const float*)d_in[0];
    const int*   ei = (const int*)d_in[1];
    const float* W1 = (const float*)d_in[2];
    const float* b1 = (const float*)d_in[3];
    const float* W2 = (const float*)d_in[4];
    const float* b2 = (const float*)d_in[5];
    const float* W3 = (const float*)d_in[6];
    const float* b3 = (const float*)d_in[7];
    float* out = (float*)d_out;

    const int n = in_sizes[0] / 128;
    const int E = in_sizes[1] / 2;
    const int* src = ei;
    const int* dst = ei + E;

    float* bufA; float* bufB;
    cudaGetSymbolAddress((void**)&bufA, g_bufA);
    cudaGetSymbolAddress((void**)&bufB, g_bufB);

    const size_t sm128 = (size_t)(128 * 128 + 64 * 128) * sizeof(float);  // 96 KB
    const size_t sm64  = (size_t)(128 * 64 + 64 * 128) * sizeof(float);   // 64 KB
    cudaFuncSetAttribute(k_gemm<128, 128, false>,
                         cudaFuncAttributeMaxDynamicSharedMemorySize, (int)sm128);
    cudaFuncSetAttribute(k_gemm<128, 128, true>,
                         cudaFuncAttributeMaxDynamicSharedMemorySize, (int)sm128);
    cudaFuncSetAttribute(k_gemm<128, 64, true>,
                         cudaFuncAttributeMaxDynamicSharedMemorySize, (int)sm64);

    const int TB = 256;
    const int gN  = (n + TB - 1) / TB;
    const int gE  = (E + TB - 1) / TB;
    const int gM  = (n + 63) / 64;
    const int gAg = (n * 32 + TB - 1) / TB;   // warp per node
    const int nch = (n + 1023) / 1024;

    // normalization + CSR build (once; shared by all 3 layers)
    k_deg_init<<<gN, TB>>>(n);
    k_deg_count<<<gE, TB>>>(dst, E);
    k_dis<<<gN, TB>>>(n);
    k_scan_chunk<<<nch, 1024>>>(n);
    k_scan_top<<<1, 128>>>(nch);
    k_scan_add<<<gN, TB>>>(n);
    k_csr_fill<<<gE, TB>>>(src, dst, E);

    // layer 1
    k_gemm<128, 128, false><<<gM, TB, sm128>>>(x, W1, bufA, n);
    k_aggr<128><<<gAg, TB>>>(bufA, b1, bufB, n);

    // layer 2
    k_gemm<128, 128, true><<<gM, TB, sm128>>>(bufB, W2, bufA, n);
    k_aggr<128><<<gAg, TB>>>(bufA, b2, bufB, n);

    // layer 3
    k_gemm<128, 64, true><<<gM, TB, sm64>>>(bufB, W3, bufA, n);
    k_aggr<64><<<gAg, TB>>>(bufA, b3, out, n);
}

// round 4
// speedup vs baseline: 2.0714x; 1.1845x over previous
#include <cuda_runtime.h>
#include <cstdint>

constexpr int MAXN = 100000;
constexpr int MAXE = 1600000;
constexpr int C128 = 128;

// Scratch (__device__ globals; allocation-free rule)
__device__ float g_bufA[(size_t)MAXN * C128];  // GEMM output h
__device__ float g_bufB[(size_t)MAXN * C128];  // aggregation output
__device__ float g_dis[MAXN];                  // deg^{-1/2}
__device__ int   g_deg[MAXN];                  // 1 + in-degree
__device__ int   g_rowoff[MAXN];               // CSR exclusive offsets
__device__ int   g_cur[MAXN];                  // fill cursors
__device__ int   g_chunksum[128];
__device__ int   g_chunkoff[128];
__device__ int2  g_csr[MAXE];                  // {src, norm bits}

// ---------------------------------------------------------------------------
// helpers
// ---------------------------------------------------------------------------
__device__ __forceinline__ uint32_t f2tf32(float f) {
    uint32_t r;
    asm("cvt.rn.tf32.f32 %0, %1;" : "=r"(r) : "f"(f));
    return r;
}
__device__ __forceinline__ void mma_tf32(float* c, const uint32_t* a,
                                         const uint32_t* b) {
    asm volatile(
        "mma.sync.aligned.m16n8k8.row.col.f32.tf32.tf32.f32 "
        "{%0,%1,%2,%3}, {%4,%5,%6,%7}, {%8,%9}, {%0,%1,%2,%3};"
        : "+f"(c[0]), "+f"(c[1]), "+f"(c[2]), "+f"(c[3])
        : "r"(a[0]), "r"(a[1]), "r"(a[2]), "r"(a[3]), "r"(b[0]), "r"(b[1]));
}

// ---------------------------------------------------------------------------
// degree / norm
// ---------------------------------------------------------------------------
__global__ void k_deg_init(int n) {
    int i = blockIdx.x * blockDim.x + threadIdx.x;
    if (i < n) g_deg[i] = 1;
}
__global__ void k_deg_count(const int* __restrict__ dst, int e) {
    int i = blockIdx.x * blockDim.x + threadIdx.x;
    if (i < e) atomicAdd(&g_deg[dst[i]], 1);
}
__global__ void k_dis(int n) {
    int i = blockIdx.x * blockDim.x + threadIdx.x;
    if (i < n) g_dis[i] = rsqrtf((float)g_deg[i]);
}

// ---------------------------------------------------------------------------
// 2-level exclusive scan
// ---------------------------------------------------------------------------
__global__ __launch_bounds__(1024) void k_scan_chunk(int n) {
    __shared__ int sm[1024];
    int gid = blockIdx.x * 1024 + threadIdx.x;
    int v = (gid < n) ? (g_deg[gid] - 1) : 0;
    sm[threadIdx.x] = v;
    __syncthreads();
#pragma unroll
    for (int off = 1; off < 1024; off <<= 1) {
        int t = (threadIdx.x >= off) ? sm[threadIdx.x - off] : 0;
        __syncthreads();
        sm[threadIdx.x] += t;
        __syncthreads();
    }
    if (gid < n) g_rowoff[gid] = sm[threadIdx.x] - v;
    if (threadIdx.x == 1023) g_chunksum[blockIdx.x] = sm[1023];
}
__global__ void k_scan_top(int nch) {
    __shared__ int sm[128];
    int v = (threadIdx.x < nch) ? g_chunksum[threadIdx.x] : 0;
    sm[threadIdx.x] = v;
    __syncthreads();
#pragma unroll
    for (int off = 1; off < 128; off <<= 1) {
        int t = (threadIdx.x >= off) ? sm[threadIdx.x - off] : 0;
        __syncthreads();
        sm[threadIdx.x] += t;
        __syncthreads();
    }
    if (threadIdx.x < nch) g_chunkoff[threadIdx.x] = sm[threadIdx.x] - v;
}
__global__ void k_scan_add(int n) {
    int i = blockIdx.x * blockDim.x + threadIdx.x;
    if (i < n) {
        int o = g_rowoff[i] + g_chunkoff[i >> 10];
        g_rowoff[i] = o;
        g_cur[i] = o;
    }
}
__global__ void k_csr_fill(const int* __restrict__ src,
                           const int* __restrict__ dst, int E) {
    int e = blockIdx.x * blockDim.x + threadIdx.x;
    if (e < E) {
        int s = src[e], d = dst[e];
        int pos = atomicAdd(&g_cur[d], 1);
        float nrm = g_dis[s] * g_dis[d];
        g_csr[pos] = make_int2(s, __float_as_int(nrm));
    }
}

// ---------------------------------------------------------------------------
// Tensor-core tf32 GEMM via mma.sync.m16n8k8:
//   h[n, COUT] = relu?(x)[n,128] @ W[128, COUT]
// CTA: 256 thr (8 warps), M-tile 128. Warp grid 4(M) x 2(N); warp tile
// 32 x COUT/2. A SMEM stride 132 floats, B SMEM stride COUT+8: both make the
// fragment pattern conflict-free.
// ---------------------------------------------------------------------------
template <int COUT, bool RELU>
__global__ __launch_bounds__(256) void k_mmagemm(const float* __restrict__ x,
                                                 const float* __restrict__ W,
                                                 float* __restrict__ h, int n) {
    constexpr int AS = 132;         // A row stride (floats)
    constexpr int BS = COUT + 8;    // B row stride (floats)
    constexpr int WN = COUT / 2;    // warp N-tile
    constexpr int NI = WN / 8;      // n8 sub-tiles per warp

    extern __shared__ uint32_t sm[];
    uint32_t* As = sm;              // [128][AS]
    uint32_t* Bs = sm + 128 * AS;   // [128][BS]

    const int tid = threadIdx.x;
    const int wid = tid >> 5;
    const int lane = tid & 31;
    const int m0 = blockIdx.x * 128;

    // --- Stage A (tf32 + optional relu), coalesced float4 ---
    {
        const float4* x4 = (const float4*)x;
        for (int c = tid; c < 128 * 32; c += 256) {
            int row = c >> 5, c4 = c & 31;
            int m = m0 + row;
            float4 v = make_float4(0.f, 0.f, 0.f, 0.f);
            if (m < n) {
                v = x4[(size_t)m * 32 + c4];
                if (RELU) {
                    v.x = fmaxf(v.x, 0.f); v.y = fmaxf(v.y, 0.f);
                    v.z = fmaxf(v.z, 0.f); v.w = fmaxf(v.w, 0.f);
                }
            }
            uint4 t;
            t.x = f2tf32(v.x); t.y = f2tf32(v.y);
            t.z = f2tf32(v.z); t.w = f2tf32(v.w);
            *(uint4*)(As + row * AS + c4 * 4) = t;
        }
    }
    // --- Stage B: W[k][nc] (already K-major) ---
    {
        const float4* W4 = (const float4*)W;
        for (int c = tid; c < 128 * (COUT / 4); c += 256) {
            int k = c / (COUT / 4), c4 = c % (COUT / 4);
            float4 v = W4[c];
            uint4 t;
            t.x = f2tf32(v.x); t.y = f2tf32(v.y);
            t.z = f2tf32(v.z); t.w = f2tf32(v.w);
            *(uint4*)(Bs + k * BS + c4 * 4) = t;
        }
    }
    __syncthreads();

    const int wm = wid & 3;         // M quadrant (32 rows)
    const int wn = wid >> 2;        // N half
    const int ar = wm * 32 + (lane >> 2);
    const int ac = lane & 3;
    const int bk = lane & 3;
    const int bn0 = wn * WN + (lane >> 2);

    float acc[2][NI][4];
#pragma unroll
    for (int mi = 0; mi < 2; mi++)
#pragma unroll
        for (int ni = 0; ni < NI; ni++)
#pragma unroll
            for (int j = 0; j < 4; j++) acc[mi][ni][j] = 0.f;

#pragma unroll
    for (int ks = 0; ks < 16; ks++) {
        const int k0 = ks * 8;
        uint32_t a[2][4];
#pragma unroll
        for (int mi = 0; mi < 2; mi++) {
            int r0 = ar + mi * 16;
            a[mi][0] = As[r0 * AS + k0 + ac];
            a[mi][1] = As[(r0 + 8) * AS + k0 + ac];
            a[mi][2] = As[r0 * AS + k0 + ac + 4];
            a[mi][3] = As[(r0 + 8) * AS + k0 + ac + 4];
        }
        uint32_t b[NI][2];
#pragma unroll
        for (int ni = 0; ni < NI; ni++) {
            int col = bn0 + ni * 8;
            b[ni][0] = Bs[(k0 + bk) * BS + col];
            b[ni][1] = Bs[(k0 + bk + 4) * BS + col];
        }
#pragma unroll
        for (int mi = 0; mi < 2; mi++)
#pragma unroll
            for (int ni = 0; ni < NI; ni++)
                mma_tf32(acc[mi][ni], a[mi], b[ni]);
    }

    // --- Epilogue: float2 stores ---
#pragma unroll
    for (int mi = 0; mi < 2; mi++) {
        int r_lo = m0 + wm * 32 + mi * 16 + (lane >> 2);
        int r_hi = r_lo + 8;
#pragma unroll
        for (int ni = 0; ni < NI; ni++) {
            int col = wn * WN + ni * 8 + (lane & 3) * 2;
            if (r_lo < n)
                *(float2*)(h + (size_t)r_lo * COUT + col) =
                    make_float2(acc[mi][ni][0], acc[mi][ni][1]);
            if (r_hi < n)
                *(float2*)(h + (size_t)r_hi * COUT + col) =
                    make_float2(acc[mi][ni][2], acc[mi][ni][3]);
        }
    }
}

// ---------------------------------------------------------------------------
// CSR gather-aggregate: out[i,:] = b + dis^2*h[i,:] + sum norm*h[src,:]
// ---------------------------------------------------------------------------
template <int C>
__global__ __launch_bounds__(256) void k_aggr(const float* __restrict__ h,
                                              const float* __restrict__ b,
                                              float* __restrict__ out, int n) {
    int i = (blockIdx.x * 256 + threadIdx.x) >> 5;
    int lane = threadIdx.x & 31;
    if (i >= n) return;

    float d = g_dis[i];
    float s2 = d * d;
    int e   = g_rowoff[i];
    int end = e + (g_deg[i] - 1);

    if (C == 128) {
        float4 acc = ((const float4*)b)[lane];
        float4 hv  = ((const float4*)h)[(size_t)i * 32 + lane];
        acc.x = fmaf(s2, hv.x, acc.x); acc.y = fmaf(s2, hv.y, acc.y);
        acc.z = fmaf(s2, hv.z, acc.z); acc.w = fmaf(s2, hv.w, acc.w);

        int2 ed = (e < end) ? __ldg(&g_csr[e]) : make_int2(0, 0);
        while (e < end) {
            int2 nxt = (e + 1 < end) ? __ldg(&g_csr[e + 1]) : ed;
            float nr = __int_as_float(ed.y);
            float4 v = ((const float4*)h)[(size_t)ed.x * 32 + lane];
            acc.x = fmaf(nr, v.x, acc.x); acc.y = fmaf(nr, v.y, acc.y);
            acc.z = fmaf(nr, v.z, acc.z); acc.w = fmaf(nr, v.w, acc.w);
            ed = nxt; e++;
        }
        ((float4*)out)[(size_t)i * 32 + lane] = acc;
    } else {
        float2 acc = ((const float2*)b)[lane];
        float2 hv  = ((const float2*)h)[(size_t)i * 32 + lane];
        acc.x = fmaf(s2, hv.x, acc.x); acc.y = fmaf(s2, hv.y, acc.y);

        int2 ed = (e < end) ? __ldg(&g_csr[e]) : make_int2(0, 0);
        while (e < end) {
            int2 nxt = (e + 1 < end) ? __ldg(&g_csr[e + 1]) : ed;
            float nr = __int_as_float(ed.y);
            float2 v = ((const float2*)h)[(size_t)ed.x * 32 + lane];
            acc.x = fmaf(nr, v.x, acc.x); acc.y = fmaf(nr, v.y, acc.y);
            ed = nxt; e++;
        }
        ((float2*)out)[(size_t)i * 32 + lane] = acc;
    }
}

// ---------------------------------------------------------------------------
// Launch
// ---------------------------------------------------------------------------
extern "C" void kernel_launch(void* const* d_in, const int* in_sizes, int n_in,
                              void* d_out, int out_size) {
    const float* x  = (const float*)d_in[0];
    const int*   ei = (const int*)d_in[1];
    const float* W1 = (const float*)d_in[2];
    const float* b1 = (const float*)d_in[3];
    const float* W2 = (const float*)d_in[4];
    const float* b2 = (const float*)d_in[5];
    const float* W3 = (const float*)d_in[6];
    const float* b3 = (const float*)d_in[7];
    float* out = (float*)d_out;

    const int n = in_sizes[0] / 128;
    const int E = in_sizes[1] / 2;
    const int* src = ei;
    const int* dst = ei + E;

    float* bufA; float* bufB;
    cudaGetSymbolAddress((void**)&bufA, g_bufA);
    cudaGetSymbolAddress((void**)&bufB, g_bufB);

    const size_t smG128 = (size_t)(128 * 132 + 128 * 136) * 4;  // 137,216 B
    const size_t smG64  = (size_t)(128 * 132 + 128 * 72) * 4;   // 104,448 B
    cudaFuncSetAttribute(k_mmagemm<128, false>,
                         cudaFuncAttributeMaxDynamicSharedMemorySize, (int)smG128);
    cudaFuncSetAttribute(k_mmagemm<128, true>,
                         cudaFuncAttributeMaxDynamicSharedMemorySize, (int)smG128);
    cudaFuncSetAttribute(k_mmagemm<64, true>,
                         cudaFuncAttributeMaxDynamicSharedMemorySize, (int)smG64);

    const int TB = 256;
    const int gN  = (n + TB - 1) / TB;
    const int gE  = (E + TB - 1) / TB;
    const int gM  = (n + 127) / 128;
    const int gAg = (n * 32 + TB - 1) / TB;
    const int nch = (n + 1023) / 1024;

    // normalization + CSR build (shared by all 3 layers)
    k_deg_init<<<gN, TB>>>(n);
    k_deg_count<<<gE, TB>>>(dst, E);
    k_dis<<<gN, TB>>>(n);
    k_scan_chunk<<<nch, 1024>>>(n);
    k_scan_top<<<1, 128>>>(nch);
    k_scan_add<<<gN, TB>>>(n);
    k_csr_fill<<<gE, TB>>>(src, dst, E);

    // layer 1
    k_mmagemm<128, false><<<gM, TB, smG128>>>(x, W1, bufA, n);
    k_aggr<128><<<gAg, TB>>>(bufA, b1, bufB, n);

    // layer 2
    k_mmagemm<128, true><<<gM, TB, smG128>>>(bufB, W2, bufA, n);
    k_aggr<128><<<gAg, TB>>>(bufA, b2, bufB, n);

    // layer 3
    k_mmagemm<64, true><<<gM, TB, smG64>>>(bufB, W3, bufA, n);
    k_aggr<64><<<gAg, TB>>>(bufA, b3, out, n);
}

// round 5
// speedup vs baseline: 2.5224x; 1.2177x over previous
#include <cuda_runtime.h>
#include <cstdint>

constexpr int MAXN = 100000;
constexpr int MAXE = 1600000;
constexpr int C128 = 128;

// Scratch (__device__ globals; allocation-free rule)
__device__ float g_bufA[(size_t)MAXN * C128];  // GEMM output h
__device__ float g_bufB[(size_t)MAXN * C128];  // aggregation output
__device__ float g_dis[MAXN];                  // deg^{-1/2}
__device__ int   g_deg[MAXN];                  // 1 + in-degree
__device__ int   g_rowoff[MAXN];               // CSR exclusive offsets
__device__ int   g_cur[MAXN];                  // fill cursors
__device__ int   g_chunksum[128];
__device__ int   g_chunkoff[128];
__device__ int2  g_csr[MAXE];                  // {src, norm bits}

// ---------------------------------------------------------------------------
// helpers
// ---------------------------------------------------------------------------
__device__ __forceinline__ uint32_t f2tf32(float f) {
    uint32_t r;
    asm("cvt.rn.tf32.f32 %0, %1;" : "=r"(r) : "f"(f));
    return r;
}
__device__ __forceinline__ void mma_tf32(float* c, const uint32_t* a,
                                         const uint32_t* b) {
    asm volatile(
        "mma.sync.aligned.m16n8k8.row.col.f32.tf32.tf32.f32 "
        "{%0,%1,%2,%3}, {%4,%5,%6,%7}, {%8,%9}, {%0,%1,%2,%3};"
        : "+f"(c[0]), "+f"(c[1]), "+f"(c[2]), "+f"(c[3])
        : "r"(a[0]), "r"(a[1]), "r"(a[2]), "r"(a[3]), "r"(b[0]), "r"(b[1]));
}

// ---------------------------------------------------------------------------
// degree / norm
// ---------------------------------------------------------------------------
__global__ void k_deg_init(int n) {
    int i = blockIdx.x * blockDim.x + threadIdx.x;
    if (i < n) g_deg[i] = 1;
}
__global__ void k_deg_count(const int* __restrict__ dst, int e) {
    int i = blockIdx.x * blockDim.x + threadIdx.x;
    if (i < e) atomicAdd(&g_deg[dst[i]], 1);
}
__global__ void k_dis(int n) {
    int i = blockIdx.x * blockDim.x + threadIdx.x;
    if (i < n) g_dis[i] = rsqrtf((float)g_deg[i]);
}

// ---------------------------------------------------------------------------
// 2-level exclusive scan
// ---------------------------------------------------------------------------
__global__ __launch_bounds__(1024) void k_scan_chunk(int n) {
    __shared__ int sm[1024];
    int gid = blockIdx.x * 1024 + threadIdx.x;
    int v = (gid < n) ? (g_deg[gid] - 1) : 0;
    sm[threadIdx.x] = v;
    __syncthreads();
#pragma unroll
    for (int off = 1; off < 1024; off <<= 1) {
        int t = (threadIdx.x >= off) ? sm[threadIdx.x - off] : 0;
        __syncthreads();
        sm[threadIdx.x] += t;
        __syncthreads();
    }
    if (gid < n) g_rowoff[gid] = sm[threadIdx.x] - v;
    if (threadIdx.x == 1023) g_chunksum[blockIdx.x] = sm[1023];
}
__global__ void k_scan_top(int nch) {
    __shared__ int sm[128];
    int v = (threadIdx.x < nch) ? g_chunksum[threadIdx.x] : 0;
    sm[threadIdx.x] = v;
    __syncthreads();
#pragma unroll
    for (int off = 1; off < 128; off <<= 1) {
        int t = (threadIdx.x >= off) ? sm[threadIdx.x - off] : 0;
        __syncthreads();
        sm[threadIdx.x] += t;
        __syncthreads();
    }
    if (threadIdx.x < nch) g_chunkoff[threadIdx.x] = sm[threadIdx.x] - v;
}
__global__ void k_scan_add(int n) {
    int i = blockIdx.x * blockDim.x + threadIdx.x;
    if (i < n) {
        int o = g_rowoff[i] + g_chunkoff[i >> 10];
        g_rowoff[i] = o;
        g_cur[i] = o;
    }
}
__global__ void k_csr_fill(const int* __restrict__ src,
                           const int* __restrict__ dst, int E) {
    int e = blockIdx.x * blockDim.x + threadIdx.x;
    if (e < E) {
        int s = src[e], d = dst[e];
        int pos = atomicAdd(&g_cur[d], 1);
        float nrm = g_dis[s] * g_dis[d];
        g_csr[pos] = make_int2(s, __float_as_int(nrm));
    }
}

// ---------------------------------------------------------------------------
// Tensor-core tf32 GEMM via mma.sync.m16n8k8:
//   h[n, COUT] = relu?(x)[n,128] @ W[128, COUT]
// CTA: 256 thr (8 warps), M-tile 128. Warp grid 4(M) x 2(N).
// B (weights) staged in SMEM (stride COUT+8, conflict-free); A fragments
// loaded DIRECTLY from global (8 rows x 32B sectors per fragment pair, L1
// reuse across the 2 N-half warps). SMEM = B only -> 2 CTAs/SM.
// ---------------------------------------------------------------------------
template <int COUT, bool RELU>
__global__ __launch_bounds__(256, 2) void k_mmagemm(const float* __restrict__ x,
                                                    const float* __restrict__ W,
                                                    float* __restrict__ h, int n) {
    constexpr int BS = COUT + 8;    // B row stride (floats)
    constexpr int WN = COUT / 2;    // warp N-tile
    constexpr int NI = WN / 8;      // n8 sub-tiles per warp

    extern __shared__ uint32_t sm[];
    uint32_t* Bs = sm;              // [128][BS]

    const int tid = threadIdx.x;
    const int wid = tid >> 5;
    const int lane = tid & 31;
    const int m0 = blockIdx.x * 128;

    // --- Stage B: W[k][nc] (K-major), tf32 ---
    {
        const float4* W4 = (const float4*)W;
        for (int c = tid; c < 128 * (COUT / 4); c += 256) {
            int k = c / (COUT / 4), c4 = c % (COUT / 4);
            float4 v = W4[c];
            uint4 t;
            t.x = f2tf32(v.x); t.y = f2tf32(v.y);
            t.z = f2tf32(v.z); t.w = f2tf32(v.w);
            *(uint4*)(Bs + k * BS + c4 * 4) = t;
        }
    }
    __syncthreads();

    const int wm = wid & 3;         // M quadrant (32 rows)
    const int wn = wid >> 2;        // N half
    const int ac = lane & 3;
    const int bk = lane & 3;
    const int bn0 = wn * WN + (lane >> 2);

    // Per-warp A row bases (rows for mi=0: r0, r0+8; mi=1: r0+16, r0+24)
    const int r_base = m0 + wm * 32 + (lane >> 2);
    const float* ap0 = x + (size_t)r_base * 128 + ac;          // mi=0 lo
    const bool v00 = (r_base      < n), v01 = (r_base + 8  < n);
    const bool v10 = (r_base + 16 < n), v11 = (r_base + 24 < n);

    float acc[2][NI][4];
#pragma unroll
    for (int mi = 0; mi < 2; mi++)
#pragma unroll
        for (int ni = 0; ni < NI; ni++)
#pragma unroll
            for (int j = 0; j < 4; j++) acc[mi][ni][j] = 0.f;

#pragma unroll
    for (int ks = 0; ks < 16; ks++) {
        const int k0 = ks * 8;
        // A fragments direct from global (+relu +tf32)
        uint32_t a[2][4];
#pragma unroll
        for (int mi = 0; mi < 2; mi++) {
            const float* p = ap0 + mi * (16 * 128) + k0;
            const bool vlo = mi ? v10 : v00;
            const bool vhi = mi ? v11 : v01;
            float f0 = vlo ? __ldg(p)             : 0.f;
            float f1 = vhi ? __ldg(p + 8 * 128)    : 0.f;
            float f2 = vlo ? __ldg(p + 4)          : 0.f;
            float f3 = vhi ? __ldg(p + 8 * 128 + 4): 0.f;
            if (RELU) {
                f0 = fmaxf(f0, 0.f); f1 = fmaxf(f1, 0.f);
                f2 = fmaxf(f2, 0.f); f3 = fmaxf(f3, 0.f);
            }
            a[mi][0] = f2tf32(f0); a[mi][1] = f2tf32(f1);
            a[mi][2] = f2tf32(f2); a[mi][3] = f2tf32(f3);
        }
        // B fragments from SMEM (conflict-free)
        uint32_t b[NI][2];
#pragma unroll
        for (int ni = 0; ni < NI; ni++) {
            int col = bn0 + ni * 8;
            b[ni][0] = Bs[(k0 + bk) * BS + col];
            b[ni][1] = Bs[(k0 + bk + 4) * BS + col];
        }
#pragma unroll
        for (int mi = 0; mi < 2; mi++)
#pragma unroll
            for (int ni = 0; ni < NI; ni++)
                mma_tf32(acc[mi][ni], a[mi], b[ni]);
    }

    // --- Epilogue: float2 stores ---
#pragma unroll
    for (int mi = 0; mi < 2; mi++) {
        int r_lo = m0 + wm * 32 + mi * 16 + (lane >> 2);
        int r_hi = r_lo + 8;
#pragma unroll
        for (int ni = 0; ni < NI; ni++) {
            int col = wn * WN + ni * 8 + (lane & 3) * 2;
            if (r_lo < n)
                *(float2*)(h + (size_t)r_lo * COUT + col) =
                    make_float2(acc[mi][ni][0], acc[mi][ni][1]);
            if (r_hi < n)
                *(float2*)(h + (size_t)r_hi * COUT + col) =
                    make_float2(acc[mi][ni][2], acc[mi][ni][3]);
        }
    }
}

// ---------------------------------------------------------------------------
// CSR gather-aggregate: out[i,:] = b + dis^2*h[i,:] + sum norm*h[src,:]
// ---------------------------------------------------------------------------
template <int C>
__global__ __launch_bounds__(256) void k_aggr(const float* __restrict__ h,
                                              const float* __restrict__ b,
                                              float* __restrict__ out, int n) {
    int i = (blockIdx.x * 256 + threadIdx.x) >> 5;
    int lane = threadIdx.x & 31;
    if (i >= n) return;

    float d = g_dis[i];
    float s2 = d * d;
    int e   = g_rowoff[i];
    int end = e + (g_deg[i] - 1);

    if (C == 128) {
        float4 acc = ((const float4*)b)[lane];
        float4 hv  = ((const float4*)h)[(size_t)i * 32 + lane];
        acc.x = fmaf(s2, hv.x, acc.x); acc.y = fmaf(s2, hv.y, acc.y);
        acc.z = fmaf(s2, hv.z, acc.z); acc.w = fmaf(s2, hv.w, acc.w);

        int2 ed = (e < end) ? __ldg(&g_csr[e]) : make_int2(0, 0);
        while (e < end) {
            int2 nxt = (e + 1 < end) ? __ldg(&g_csr[e + 1]) : ed;
            float nr = __int_as_float(ed.y);
            float4 v = ((const float4*)h)[(size_t)ed.x * 32 + lane];
            acc.x = fmaf(nr, v.x, acc.x); acc.y = fmaf(nr, v.y, acc.y);
            acc.z = fmaf(nr, v.z, acc.z); acc.w = fmaf(nr, v.w, acc.w);
            ed = nxt; e++;
        }
        ((float4*)out)[(size_t)i * 32 + lane] = acc;
    } else {
        float2 acc = ((const float2*)b)[lane];
        float2 hv  = ((const float2*)h)[(size_t)i * 32 + lane];
        acc.x = fmaf(s2, hv.x, acc.x); acc.y = fmaf(s2, hv.y, acc.y);

        int2 ed = (e < end) ? __ldg(&g_csr[e]) : make_int2(0, 0);
        while (e < end) {
            int2 nxt = (e + 1 < end) ? __ldg(&g_csr[e + 1]) : ed;
            float nr = __int_as_float(ed.y);
            float2 v = ((const float2*)h)[(size_t)ed.x * 32 + lane];
            acc.x = fmaf(nr, v.x, acc.x); acc.y = fmaf(nr, v.y, acc.y);
            ed = nxt; e++;
        }
        ((float2*)out)[(size_t)i * 32 + lane] = acc;
    }
}

// ---------------------------------------------------------------------------
// Launch
// ---------------------------------------------------------------------------
extern "C" void kernel_launch(void* const* d_in, const int* in_sizes, int n_in,
                              void* d_out, int out_size) {
    const float* x  = (const float*)d_in[0];
    const int*   ei = (const int*)d_in[1];
    const float* W1 = (const float*)d_in[2];
    const float* b1 = (const float*)d_in[3];
    const float* W2 = (const float*)d_in[4];
    const float* b2 = (const float*)d_in[5];
    const float* W3 = (const float*)d_in[6];
    const float* b3 = (const float*)d_in[7];
    float* out = (float*)d_out;

    const int n = in_sizes[0] / 128;
    const int E = in_sizes[1] / 2;
    const int* src = ei;
    const int* dst = ei + E;

    float* bufA; float* bufB;
    cudaGetSymbolAddress((void**)&bufA, g_bufA);
    cudaGetSymbolAddress((void**)&bufB, g_bufB);

    const size_t smG128 = (size_t)(128 * 136) * 4;  // 69,632 B
    const size_t smG64  = (size_t)(128 * 72) * 4;   // 36,864 B
    cudaFuncSetAttribute(k_mmagemm<128, false>,
                         cudaFuncAttributeMaxDynamicSharedMemorySize, (int)smG128);
    cudaFuncSetAttribute(k_mmagemm<128, true>,
                         cudaFuncAttributeMaxDynamicSharedMemorySize, (int)smG128);
    cudaFuncSetAttribute(k_mmagemm<64, true>,
                         cudaFuncAttributeMaxDynamicSharedMemorySize, (int)smG64);

    const int TB = 256;
    const int gN  = (n + TB - 1) / TB;
    const int gE  = (E + TB - 1) / TB;
    const int gM  = (n + 127) / 128;
    const int gAg = (n * 32 + TB - 1) / TB;
    const int nch = (n + 1023) / 1024;

    // normalization + CSR build (shared by all 3 layers)
    k_deg_init<<<gN, TB>>>(n);
    k_deg_count<<<gE, TB>>>(dst, E);
    k_dis<<<gN, TB>>>(n);
    k_scan_chunk<<<nch, 1024>>>(n);
    k_scan_top<<<1, 128>>>(nch);
    k_scan_add<<<gN, TB>>>(n);
    k_csr_fill<<<gE, TB>>>(src, dst, E);

    // layer 1
    k_mmagemm<128, false><<<gM, TB, smG128>>>(x, W1, bufA, n);
    k_aggr<128><<<gAg, TB>>>(bufA, b1, bufB, n);

    // layer 2
    k_mmagemm<128, true><<<gM, TB, smG128>>>(bufB, W2, bufA, n);
    k_aggr<128><<<gAg, TB>>>(bufA, b2, bufB, n);

    // layer 3
    k_mmagemm<64, true><<<gM, TB, smG64>>>(bufB, W3, bufA, n);
    k_aggr<64><<<gAg, TB>>>(bufA, b3, out, n);
}

// round 6
// speedup vs baseline: 2.6334x; 1.0440x over previous
#include <cuda_runtime.h>
#include <cuda_fp16.h>
#include <cstdint>

constexpr int MAXN = 100000;
constexpr int MAXE = 1600000;
constexpr int C128 = 128;

// Scratch (__device__ globals; allocation-free rule)
__device__ __half g_bufH[(size_t)MAXN * C128];  // GEMM output h (fp16 messages)
__device__ float  g_bufF[(size_t)MAXN * C128];  // aggregation output (fp32)
__device__ float  g_dis[MAXN];                  // deg^{-1/2}
__device__ int    g_deg[MAXN];                  // 1 + in-degree
__device__ int    g_rowoff[MAXN];               // CSR exclusive offsets
__device__ int    g_cur[MAXN];                  // fill cursors
__device__ int    g_chunksum[128];
__device__ int    g_chunkoff[128];
__device__ int2   g_csr[MAXE];                  // {src, norm bits}

// ---------------------------------------------------------------------------
// helpers
// ---------------------------------------------------------------------------
__device__ __forceinline__ uint32_t f2tf32(float f) {
    uint32_t r;
    asm("cvt.rn.tf32.f32 %0, %1;" : "=r"(r) : "f"(f));
    return r;
}
__device__ __forceinline__ void mma_tf32(float* c, const uint32_t* a,
                                         const uint32_t* b) {
    asm volatile(
        "mma.sync.aligned.m16n8k8.row.col.f32.tf32.tf32.f32 "
        "{%0,%1,%2,%3}, {%4,%5,%6,%7}, {%8,%9}, {%0,%1,%2,%3};"
        : "+f"(c[0]), "+f"(c[1]), "+f"(c[2]), "+f"(c[3])
        : "r"(a[0]), "r"(a[1]), "r"(a[2]), "r"(a[3]), "r"(b[0]), "r"(b[1]));
}

// ---------------------------------------------------------------------------
// degree / norm
// ---------------------------------------------------------------------------
__global__ void k_deg_init(int n) {
    int i = blockIdx.x * blockDim.x + threadIdx.x;
    if (i < n) g_deg[i] = 1;
}
__global__ void k_deg_count(const int* __restrict__ dst, int e) {
    int i = blockIdx.x * blockDim.x + threadIdx.x;
    if (i < e) atomicAdd(&g_deg[dst[i]], 1);
}
__global__ void k_dis(int n) {
    int i = blockIdx.x * blockDim.x + threadIdx.x;
    if (i < n) g_dis[i] = rsqrtf((float)g_deg[i]);
}

// ---------------------------------------------------------------------------
// 2-level exclusive scan
// ---------------------------------------------------------------------------
__global__ __launch_bounds__(1024) void k_scan_chunk(int n) {
    __shared__ int sm[1024];
    int gid = blockIdx.x * 1024 + threadIdx.x;
    int v = (gid < n) ? (g_deg[gid] - 1) : 0;
    sm[threadIdx.x] = v;
    __syncthreads();
#pragma unroll
    for (int off = 1; off < 1024; off <<= 1) {
        int t = (threadIdx.x >= off) ? sm[threadIdx.x - off] : 0;
        __syncthreads();
        sm[threadIdx.x] += t;
        __syncthreads();
    }
    if (gid < n) g_rowoff[gid] = sm[threadIdx.x] - v;
    if (threadIdx.x == 1023) g_chunksum[blockIdx.x] = sm[1023];
}
__global__ void k_scan_top(int nch) {
    __shared__ int sm[128];
    int v = (threadIdx.x < nch) ? g_chunksum[threadIdx.x] : 0;
    sm[threadIdx.x] = v;
    __syncthreads();
#pragma unroll
    for (int off = 1; off < 128; off <<= 1) {
        int t = (threadIdx.x >= off) ? sm[threadIdx.x - off] : 0;
        __syncthreads();
        sm[threadIdx.x] += t;
        __syncthreads();
    }
    if (threadIdx.x < nch) g_chunkoff[threadIdx.x] = sm[threadIdx.x] - v;
}
__global__ void k_scan_add(int n) {
    int i = blockIdx.x * blockDim.x + threadIdx.x;
    if (i < n) {
        int o = g_rowoff[i] + g_chunkoff[i >> 10];
        g_rowoff[i] = o;
        g_cur[i] = o;
    }
}
__global__ void k_csr_fill(const int* __restrict__ src,
                           const int* __restrict__ dst, int E) {
    int e = blockIdx.x * blockDim.x + threadIdx.x;
    if (e < E) {
        int s = src[e], d = dst[e];
        int pos = atomicAdd(&g_cur[d], 1);
        float nrm = g_dis[s] * g_dis[d];
        g_csr[pos] = make_int2(s, __float_as_int(nrm));
    }
}

// ---------------------------------------------------------------------------
// Tensor-core tf32 GEMM (mma.sync.m16n8k8):
//   h16[n, COUT] = fp16( relu?(x)[n,128] @ W[128, COUT] )
// CTA: 256 thr, M-tile 128, warps 4(M) x 2(N). B in SMEM (stride COUT+8),
// A fragments direct from global. Epilogue emits packed half2.
// ---------------------------------------------------------------------------
template <int COUT, bool RELU>
__global__ __launch_bounds__(256, 2) void k_mmagemm(const float* __restrict__ x,
                                                    const float* __restrict__ W,
                                                    __half* __restrict__ h, int n) {
    constexpr int BS = COUT + 8;
    constexpr int WN = COUT / 2;
    constexpr int NI = WN / 8;

    extern __shared__ uint32_t sm[];
    uint32_t* Bs = sm;

    const int tid = threadIdx.x;
    const int wid = tid >> 5;
    const int lane = tid & 31;
    const int m0 = blockIdx.x * 128;

    // --- Stage B: W[k][nc] (K-major), tf32 ---
    {
        const float4* W4 = (const float4*)W;
        for (int c = tid; c < 128 * (COUT / 4); c += 256) {
            int k = c / (COUT / 4), c4 = c % (COUT / 4);
            float4 v = W4[c];
            uint4 t;
            t.x = f2tf32(v.x); t.y = f2tf32(v.y);
            t.z = f2tf32(v.z); t.w = f2tf32(v.w);
            *(uint4*)(Bs + k * BS + c4 * 4) = t;
        }
    }
    __syncthreads();

    const int wm = wid & 3;
    const int wn = wid >> 2;
    const int ac = lane & 3;
    const int bk = lane & 3;
    const int bn0 = wn * WN + (lane >> 2);

    const int r_base = m0 + wm * 32 + (lane >> 2);
    const float* ap0 = x + (size_t)r_base * 128 + ac;
    const bool v00 = (r_base      < n), v01 = (r_base + 8  < n);
    const bool v10 = (r_base + 16 < n), v11 = (r_base + 24 < n);

    float acc[2][NI][4];
#pragma unroll
    for (int mi = 0; mi < 2; mi++)
#pragma unroll
        for (int ni = 0; ni < NI; ni++)
#pragma unroll
            for (int j = 0; j < 4; j++) acc[mi][ni][j] = 0.f;

#pragma unroll
    for (int ks = 0; ks < 16; ks++) {
        const int k0 = ks * 8;
        uint32_t a[2][4];
#pragma unroll
        for (int mi = 0; mi < 2; mi++) {
            const float* p = ap0 + mi * (16 * 128) + k0;
            const bool vlo = mi ? v10 : v00;
            const bool vhi = mi ? v11 : v01;
            float f0 = vlo ? __ldg(p)              : 0.f;
            float f1 = vhi ? __ldg(p + 8 * 128)    : 0.f;
            float f2 = vlo ? __ldg(p + 4)          : 0.f;
            float f3 = vhi ? __ldg(p + 8 * 128 + 4): 0.f;
            if (RELU) {
                f0 = fmaxf(f0, 0.f); f1 = fmaxf(f1, 0.f);
                f2 = fmaxf(f2, 0.f); f3 = fmaxf(f3, 0.f);
            }
            a[mi][0] = f2tf32(f0); a[mi][1] = f2tf32(f1);
            a[mi][2] = f2tf32(f2); a[mi][3] = f2tf32(f3);
        }
        uint32_t b[NI][2];
#pragma unroll
        for (int ni = 0; ni < NI; ni++) {
            int col = bn0 + ni * 8;
            b[ni][0] = Bs[(k0 + bk) * BS + col];
            b[ni][1] = Bs[(k0 + bk + 4) * BS + col];
        }
#pragma unroll
        for (int mi = 0; mi < 2; mi++)
#pragma unroll
            for (int ni = 0; ni < NI; ni++)
                mma_tf32(acc[mi][ni], a[mi], b[ni]);
    }

    // --- Epilogue: packed half2 stores (channel pair col, col+1) ---
    __half2* h2 = (__half2*)h;
#pragma unroll
    for (int mi = 0; mi < 2; mi++) {
        int r_lo = m0 + wm * 32 + mi * 16 + (lane >> 2);
        int r_hi = r_lo + 8;
#pragma unroll
        for (int ni = 0; ni < NI; ni++) {
            int col = wn * WN + ni * 8 + (lane & 3) * 2;
            if (r_lo < n)
                h2[(size_t)r_lo * (COUT / 2) + col / 2] =
                    __floats2half2_rn(acc[mi][ni][0], acc[mi][ni][1]);
            if (r_hi < n)
                h2[(size_t)r_hi * (COUT / 2) + col / 2] =
                    __floats2half2_rn(acc[mi][ni][2], acc[mi][ni][3]);
        }
    }
}

// ---------------------------------------------------------------------------
// CSR gather-aggregate (fp16 messages, fp32 accumulate):
// out[i,:] = b + dis^2*h[i,:] + sum norm*h[src,:]
// Warp per node. C=128: lane owns 4 ch (uint2 = 4 halves); C=64: 2 ch.
// ---------------------------------------------------------------------------
template <int C>
__global__ __launch_bounds__(256) void k_aggr(const __half* __restrict__ h,
                                              const float* __restrict__ b,
                                              float* __restrict__ out, int n) {
    int i = (blockIdx.x * 256 + threadIdx.x) >> 5;
    int lane = threadIdx.x & 31;
    if (i >= n) return;

    float d = g_dis[i];
    float s2 = d * d;
    int e   = g_rowoff[i];
    int end = e + (g_deg[i] - 1);

    if (C == 128) {
        const uint2* h4 = (const uint2*)h;   // 4 halves per elem, 32 per row
        float4 acc = ((const float4*)b)[lane];
        {
            uint2 u = h4[(size_t)i * 32 + lane];
            float2 p0 = __half22float2(*(const __half2*)&u.x);
            float2 p1 = __half22float2(*(const __half2*)&u.y);
            acc.x = fmaf(s2, p0.x, acc.x); acc.y = fmaf(s2, p0.y, acc.y);
            acc.z = fmaf(s2, p1.x, acc.z); acc.w = fmaf(s2, p1.y, acc.w);
        }
        int2 ed = (e < end) ? __ldg(&g_csr[e]) : make_int2(0, 0);
        while (e < end) {
            int2 nxt = (e + 1 < end) ? __ldg(&g_csr[e + 1]) : ed;
            float nr = __int_as_float(ed.y);
            uint2 u = h4[(size_t)ed.x * 32 + lane];
            float2 p0 = __half22float2(*(const __half2*)&u.x);
            float2 p1 = __half22float2(*(const __half2*)&u.y);
            acc.x = fmaf(nr, p0.x, acc.x); acc.y = fmaf(nr, p0.y, acc.y);
            acc.z = fmaf(nr, p1.x, acc.z); acc.w = fmaf(nr, p1.y, acc.w);
            ed = nxt; e++;
        }
        ((float4*)out)[(size_t)i * 32 + lane] = acc;
    } else {  // C == 64
        const uint32_t* h2 = (const uint32_t*)h;  // 2 halves, 32 per row
        float2 acc = ((const float2*)b)[lane];
        {
            uint32_t u = h2[(size_t)i * 32 + lane];
            float2 p = __half22float2(*(const __half2*)&u);
            acc.x = fmaf(s2, p.x, acc.x); acc.y = fmaf(s2, p.y, acc.y);
        }
        int2 ed = (e < end) ? __ldg(&g_csr[e]) : make_int2(0, 0);
        while (e < end) {
            int2 nxt = (e + 1 < end) ? __ldg(&g_csr[e + 1]) : ed;
            float nr = __int_as_float(ed.y);
            uint32_t u = h2[(size_t)ed.x * 32 + lane];
            float2 p = __half22float2(*(const __half2*)&u);
            acc.x = fmaf(nr, p.x, acc.x); acc.y = fmaf(nr, p.y, acc.y);
            ed = nxt; e++;
        }
        ((float2*)out)[(size_t)i * 32 + lane] = acc;
    }
}

// ---------------------------------------------------------------------------
// Launch
// ---------------------------------------------------------------------------
extern "C" void kernel_launch(void* const* d_in, const int* in_sizes, int n_in,
                              void* d_out, int out_size) {
    const float* x  = (const float*)d_in[0];
    const int*   ei = (const int*)d_in[1];
    const float* W1 = (const float*)d_in[2];
    const float* b1 = (const float*)d_in[3];
    const float* W2 = (const float*)d_in[4];
    const float* b2 = (const float*)d_in[5];
    const float* W3 = (const float*)d_in[6];
    const float* b3 = (const float*)d_in[7];
    float* out = (float*)d_out;

    const int n = in_sizes[0] / 128;
    const int E = in_sizes[1] / 2;
    const int* src = ei;
    const int* dst = ei + E;

    __half* bufH; float* bufF;
    cudaGetSymbolAddress((void**)&bufH, g_bufH);
    cudaGetSymbolAddress((void**)&bufF, g_bufF);

    const size_t smG128 = (size_t)(128 * 136) * 4;  // 69,632 B
    const size_t smG64  = (size_t)(128 * 72) * 4;   // 36,864 B
    cudaFuncSetAttribute(k_mmagemm<128, false>,
                         cudaFuncAttributeMaxDynamicSharedMemorySize, (int)smG128);
    cudaFuncSetAttribute(k_mmagemm<128, true>,
                         cudaFuncAttributeMaxDynamicSharedMemorySize, (int)smG128);
    cudaFuncSetAttribute(k_mmagemm<64, true>,
                         cudaFuncAttributeMaxDynamicSharedMemorySize, (int)smG64);

    const int TB = 256;
    const int gN  = (n + TB - 1) / TB;
    const int gE  = (E + TB - 1) / TB;
    const int gM  = (n + 127) / 128;
    const int gAg = (n * 32 + TB - 1) / TB;
    const int nch = (n + 1023) / 1024;

    // normalization + CSR build (shared by all 3 layers)
    k_deg_init<<<gN, TB>>>(n);
    k_deg_count<<<gE, TB>>>(dst, E);
    k_dis<<<gN, TB>>>(n);
    k_scan_chunk<<<nch, 1024>>>(n);
    k_scan_top<<<1, 128>>>(nch);
    k_scan_add<<<gN, TB>>>(n);
    k_csr_fill<<<gE, TB>>>(src, dst, E);

    // layer 1
    k_mmagemm<128, false><<<gM, TB, smG128>>>(x, W1, bufH, n);
    k_aggr<128><<<gAg, TB>>>(bufH, b1, bufF, n);

    // layer 2
    k_mmagemm<128, true><<<gM, TB, smG128>>>(bufF, W2, bufH, n);
    k_aggr<128><<<gAg, TB>>>(bufH, b2, bufF, n);

    // layer 3
    k_mmagemm<64, true><<<gM, TB, smG64>>>(bufF, W3, bufH, n);
    k_aggr<64><<<gAg, TB>>>(bufH, b3, out, n);
}

// round 8
// speedup vs baseline: 2.7076x; 1.0282x over previous
#include <cuda_runtime.h>
#include <cuda_fp16.h>
#include <cstdint>

constexpr int MAXN = 100000;
constexpr int MAXE = 1600000;
constexpr int C128 = 128;

// Scratch (__device__ globals; allocation-free rule)
__device__ __half g_bufH[(size_t)MAXN * C128];  // GEMM output h (fp16 messages)
__device__ float  g_bufF[(size_t)MAXN * C128];  // aggregation output (fp32)
__device__ float  g_dis[MAXN];                  // deg^{-1/2}
__device__ int    g_deg[MAXN];                  // 1 + in-degree
__device__ int    g_rowoff[MAXN];               // CSR exclusive offsets
__device__ int    g_cur[MAXN];                  // fill cursors
__device__ int    g_chunksum[128];
__device__ int    g_chunkoff[128];
__device__ int2   g_csr[MAXE];                  // {src, norm bits}

// ---------------------------------------------------------------------------
// helpers
// ---------------------------------------------------------------------------
__device__ __forceinline__ uint32_t f2tf32(float f) {
    uint32_t r;
    asm("cvt.rn.tf32.f32 %0, %1;" : "=r"(r) : "f"(f));
    return r;
}
__device__ __forceinline__ void mma_tf32(float* c, const uint32_t* a,
                                         const uint32_t* b) {
    asm volatile(
        "mma.sync.aligned.m16n8k8.row.col.f32.tf32.tf32.f32 "
        "{%0,%1,%2,%3}, {%4,%5,%6,%7}, {%8,%9}, {%0,%1,%2,%3};"
        : "+f"(c[0]), "+f"(c[1]), "+f"(c[2]), "+f"(c[3])
        : "r"(a[0]), "r"(a[1]), "r"(a[2]), "r"(a[3]), "r"(b[0]), "r"(b[1]));
}

// ---------------------------------------------------------------------------
// degree / norm
// ---------------------------------------------------------------------------
__global__ void k_deg_init(int n) {
    int i = blockIdx.x * blockDim.x + threadIdx.x;
    if (i < n) g_deg[i] = 1;
}
__global__ void k_deg_count(const int* __restrict__ dst, int e) {
    int i = blockIdx.x * blockDim.x + threadIdx.x;
    if (i < e) atomicAdd(&g_deg[dst[i]], 1);
}
__global__ void k_dis(int n) {
    int i = blockIdx.x * blockDim.x + threadIdx.x;
    if (i < n) g_dis[i] = rsqrtf((float)g_deg[i]);
}

// ---------------------------------------------------------------------------
// 2-level exclusive scan
// ---------------------------------------------------------------------------
__global__ __launch_bounds__(1024) void k_scan_chunk(int n) {
    __shared__ int sm[1024];
    int gid = blockIdx.x * 1024 + threadIdx.x;
    int v = (gid < n) ? (g_deg[gid] - 1) : 0;
    sm[threadIdx.x] = v;
    __syncthreads();
#pragma unroll
    for (int off = 1; off < 1024; off <<= 1) {
        int t = (threadIdx.x >= off) ? sm[threadIdx.x - off] : 0;
        __syncthreads();
        sm[threadIdx.x] += t;
        __syncthreads();
    }
    if (gid < n) g_rowoff[gid] = sm[threadIdx.x] - v;
    if (threadIdx.x == 1023) g_chunksum[blockIdx.x] = sm[1023];
}
__global__ void k_scan_top(int nch) {
    __shared__ int sm[128];
    int v = (threadIdx.x < nch) ? g_chunksum[threadIdx.x] : 0;
    sm[threadIdx.x] = v;
    __syncthreads();
#pragma unroll
    for (int off = 1; off < 128; off <<= 1) {
        int t = (threadIdx.x >= off) ? sm[threadIdx.x - off] : 0;
        __syncthreads();
        sm[threadIdx.x] += t;
        __syncthreads();
    }
    if (threadIdx.x < nch) g_chunkoff[threadIdx.x] = sm[threadIdx.x] - v;
}
__global__ void k_scan_add(int n) {
    int i = blockIdx.x * blockDim.x + threadIdx.x;
    if (i < n) {
        int o = g_rowoff[i] + g_chunkoff[i >> 10];
        g_rowoff[i] = o;
        g_cur[i] = o;
    }
}
__global__ void k_csr_fill(const int* __restrict__ src,
                           const int* __restrict__ dst, int E) {
    int e = blockIdx.x * blockDim.x + threadIdx.x;
    if (e < E) {
        int s = src[e], d = dst[e];
        int pos = atomicAdd(&g_cur[d], 1);
        float nrm = g_dis[s] * g_dis[d];
        g_csr[pos] = make_int2(s, __float_as_int(nrm));
    }
}

// ---------------------------------------------------------------------------
// Tensor-core tf32 GEMM (mma.sync.m16n8k8):
//   h16[n, COUT] = fp16( relu?(x)[n,128] @ W[128, COUT] )
// ---------------------------------------------------------------------------
template <int COUT, bool RELU>
__global__ __launch_bounds__(256, 2) void k_mmagemm(const float* __restrict__ x,
                                                    const float* __restrict__ W,
                                                    __half* __restrict__ h, int n) {
    constexpr int BS = COUT + 8;
    constexpr int WN = COUT / 2;
    constexpr int NI = WN / 8;

    extern __shared__ uint32_t sm[];
    uint32_t* Bs = sm;

    const int tid = threadIdx.x;
    const int wid = tid >> 5;
    const int lane = tid & 31;
    const int m0 = blockIdx.x * 128;

    {
        const float4* W4 = (const float4*)W;
        for (int c = tid; c < 128 * (COUT / 4); c += 256) {
            int k = c / (COUT / 4), c4 = c % (COUT / 4);
            float4 v = W4[c];
            uint4 t;
            t.x = f2tf32(v.x); t.y = f2tf32(v.y);
            t.z = f2tf32(v.z); t.w = f2tf32(v.w);
            *(uint4*)(Bs + k * BS + c4 * 4) = t;
        }
    }
    __syncthreads();

    const int wm = wid & 3;
    const int wn = wid >> 2;
    const int ac = lane & 3;
    const int bk = lane & 3;
    const int bn0 = wn * WN + (lane >> 2);

    const int r_base = m0 + wm * 32 + (lane >> 2);
    const float* ap0 = x + (size_t)r_base * 128 + ac;
    const bool v00 = (r_base      < n), v01 = (r_base + 8  < n);
    const bool v10 = (r_base + 16 < n), v11 = (r_base + 24 < n);

    float acc[2][NI][4];
#pragma unroll
    for (int mi = 0; mi < 2; mi++)
#pragma unroll
        for (int ni = 0; ni < NI; ni++)
#pragma unroll
            for (int j = 0; j < 4; j++) acc[mi][ni][j] = 0.f;

#pragma unroll
    for (int ks = 0; ks < 16; ks++) {
        const int k0 = ks * 8;
        uint32_t a[2][4];
#pragma unroll
        for (int mi = 0; mi < 2; mi++) {
            const float* p = ap0 + mi * (16 * 128) + k0;
            const bool vlo = mi ? v10 : v00;
            const bool vhi = mi ? v11 : v01;
            float f0 = vlo ? __ldg(p)              : 0.f;
            float f1 = vhi ? __ldg(p + 8 * 128)    : 0.f;
            float f2 = vlo ? __ldg(p + 4)          : 0.f;
            float f3 = vhi ? __ldg(p + 8 * 128 + 4): 0.f;
            if (RELU) {
                f0 = fmaxf(f0, 0.f); f1 = fmaxf(f1, 0.f);
                f2 = fmaxf(f2, 0.f); f3 = fmaxf(f3, 0.f);
            }
            a[mi][0] = f2tf32(f0); a[mi][1] = f2tf32(f1);
            a[mi][2] = f2tf32(f2); a[mi][3] = f2tf32(f3);
        }
        uint32_t b[NI][2];
#pragma unroll
        for (int ni = 0; ni < NI; ni++) {
            int col = bn0 + ni * 8;
            b[ni][0] = Bs[(k0 + bk) * BS + col];
            b[ni][1] = Bs[(k0 + bk + 4) * BS + col];
        }
#pragma unroll
        for (int mi = 0; mi < 2; mi++)
#pragma unroll
            for (int ni = 0; ni < NI; ni++)
                mma_tf32(acc[mi][ni], a[mi], b[ni]);
    }

    __half2* h2 = (__half2*)h;
#pragma unroll
    for (int mi = 0; mi < 2; mi++) {
        int r_lo = m0 + wm * 32 + mi * 16 + (lane >> 2);
        int r_hi = r_lo + 8;
#pragma unroll
        for (int ni = 0; ni < NI; ni++) {
            int col = wn * WN + ni * 8 + (lane & 3) * 2;
            if (r_lo < n)
                h2[(size_t)r_lo * (COUT / 2) + col / 2] =
                    __floats2half2_rn(acc[mi][ni][0], acc[mi][ni][1]);
            if (r_hi < n)
                h2[(size_t)r_hi * (COUT / 2) + col / 2] =
                    __floats2half2_rn(acc[mi][ni][2], acc[mi][ni][3]);
        }
    }
}

// ---------------------------------------------------------------------------
// CSR gather-aggregate (fp16 messages, fp32 accumulate), 4-wide unrolled
// edge loop for MLP: out[i,:] = b + dis^2*h[i,:] + sum norm*h[src,:]
// ---------------------------------------------------------------------------
template <int C>
__global__ __launch_bounds__(256) void k_aggr(const __half* __restrict__ h,
                                              const float* __restrict__ b,
                                              float* __restrict__ out, int n) {
    int i = (blockIdx.x * 256 + threadIdx.x) >> 5;
    int lane = threadIdx.x & 31;
    if (i >= n) return;

    float d = g_dis[i];
    float s2 = d * d;
    int e   = g_rowoff[i];
    const int end = e + (g_deg[i] - 1);

    if (C == 128) {
        const uint2* h4 = (const uint2*)h;   // 4 halves per elem, 32 per row
        float4 acc = ((const float4*)b)[lane];
        {
            uint2 u = h4[(size_t)i * 32 + lane];
            float2 p0 = __half22float2(*(const __half2*)&u.x);
            float2 p1 = __half22float2(*(const __half2*)&u.y);
            acc.x = fmaf(s2, p0.x, acc.x); acc.y = fmaf(s2, p0.y, acc.y);
            acc.z = fmaf(s2, p1.x, acc.z); acc.w = fmaf(s2, p1.y, acc.w);
        }
        // 4-wide batches: 4 descriptor LDGs, then 4 gather LDGs in flight
        for (; e + 4 <= end; e += 4) {
            int2 e0 = __ldg(&g_csr[e]);
            int2 e1 = __ldg(&g_csr[e + 1]);
            int2 e2 = __ldg(&g_csr[e + 2]);
            int2 e3 = __ldg(&g_csr[e + 3]);
            uint2 u0 = h4[(size_t)e0.x * 32 + lane];
            uint2 u1 = h4[(size_t)e1.x * 32 + lane];
            uint2 u2 = h4[(size_t)e2.x * 32 + lane];
            uint2 u3 = h4[(size_t)e3.x * 32 + lane];
            float nr;
            float2 p0, p1;
            nr = __int_as_float(e0.y);
            p0 = __half22float2(*(const __half2*)&u0.x);
            p1 = __half22float2(*(const __half2*)&u0.y);
            acc.x = fmaf(nr, p0.x, acc.x); acc.y = fmaf(nr, p0.y, acc.y);
            acc.z = fmaf(nr, p1.x, acc.z); acc.w = fmaf(nr, p1.y, acc.w);
            nr = __int_as_float(e1.y);
            p0 = __half22float2(*(const __half2*)&u1.x);
            p1 = __half22float2(*(const __half2*)&u1.y);
            acc.x = fmaf(nr, p0.x, acc.x); acc.y = fmaf(nr, p0.y, acc.y);
            acc.z = fmaf(nr, p1.x, acc.z); acc.w = fmaf(nr, p1.y, acc.w);
            nr = __int_as_float(e2.y);
            p0 = __half22float2(*(const __half2*)&u2.x);
            p1 = __half22float2(*(const __half2*)&u2.y);
            acc.x = fmaf(nr, p0.x, acc.x); acc.y = fmaf(nr, p0.y, acc.y);
            acc.z = fmaf(nr, p1.x, acc.z); acc.w = fmaf(nr, p1.y, acc.w);
            nr = __int_as_float(e3.y);
            p0 = __half22float2(*(const __half2*)&u3.x);
            p1 = __half22float2(*(const __half2*)&u3.y);
            acc.x = fmaf(nr, p0.x, acc.x); acc.y = fmaf(nr, p0.y, acc.y);
            acc.z = fmaf(nr, p1.x, acc.z); acc.w = fmaf(nr, p1.y, acc.w);
        }
        for (; e < end; e++) {
            int2 ed = __ldg(&g_csr[e]);
            float nr = __int_as_float(ed.y);
            uint2 u = h4[(size_t)ed.x * 32 + lane];
            float2 p0 = __half22float2(*(const __half2*)&u.x);
            float2 p1 = __half22float2(*(const __half2*)&u.y);
            acc.x = fmaf(nr, p0.x, acc.x); acc.y = fmaf(nr, p0.y, acc.y);
            acc.z = fmaf(nr, p1.x, acc.z); acc.w = fmaf(nr, p1.y, acc.w);
        }
        ((float4*)out)[(size_t)i * 32 + lane] = acc;
    } else {  // C == 64
        const uint32_t* h2 = (const uint32_t*)h;  // 2 halves, 32 per row
        float2 acc = ((const float2*)b)[lane];
        {
            uint32_t u = h2[(size_t)i * 32 + lane];
            float2 p = __half22float2(*(const __half2*)&u);
            acc.x = fmaf(s2, p.x, acc.x); acc.y = fmaf(s2, p.y, acc.y);
        }
        for (; e + 4 <= end; e += 4) {
            int2 e0 = __ldg(&g_csr[e]);
            int2 e1 = __ldg(&g_csr[e + 1]);
            int2 e2 = __ldg(&g_csr[e + 2]);
            int2 e3 = __ldg(&g_csr[e + 3]);
            uint32_t u0 = h2[(size_t)e0.x * 32 + lane];
            uint32_t u1 = h2[(size_t)e1.x * 32 + lane];
            uint32_t u2 = h2[(size_t)e2.x * 32 + lane];
            uint32_t u3 = h2[(size_t)e3.x * 32 + lane];
            float nr; float2 p;
            nr = __int_as_float(e0.y);
            p = __half22float2(*(const __half2*)&u0);
            acc.x = fmaf(nr, p.x, acc.x); acc.y = fmaf(nr, p.y, acc.y);
            nr = __int_as_float(e1.y);
            p = __half22float2(*(const __half2*)&u1);
            acc.x = fmaf(nr, p.x, acc.x); acc.y = fmaf(nr, p.y, acc.y);
            nr = __int_as_float(e2.y);
            p = __half22float2(*(const __half2*)&u2);
            acc.x = fmaf(nr, p.x, acc.x); acc.y = fmaf(nr, p.y, acc.y);
            nr = __int_as_float(e3.y);
            p = __half22float2(*(const __half2*)&u3);
            acc.x = fmaf(nr, p.x, acc.x); acc.y = fmaf(nr, p.y, acc.y);
        }
        for (; e < end; e++) {
            int2 ed = __ldg(&g_csr[e]);
            float nr = __int_as_float(ed.y);
            uint32_t u = h2[(size_t)ed.x * 32 + lane];
            float2 p = __half22float2(*(const __half2*)&u);
            acc.x = fmaf(nr, p.x, acc.x); acc.y = fmaf(nr, p.y, acc.y);
        }
        ((float2*)out)[(size_t)i * 32 + lane] = acc;
    }
}

// ---------------------------------------------------------------------------
// Launch
// ---------------------------------------------------------------------------
extern "C" void kernel_launch(void* const* d_in, const int* in_sizes, int n_in,
                              void* d_out, int out_size) {
    const float* x  = (const float*)d_in[0];
    const int*   ei = (const int*)d_in[1];
    const float* W1 = (const float*)d_in[2];
    const float* b1 = (const float*)d_in[3];
    const float* W2 = (const float*)d_in[4];
    const float* b2 = (const float*)d_in[5];
    const float* W3 = (const float*)d_in[6];
    const float* b3 = (const float*)d_in[7];
    float* out = (float*)d_out;

    const int n = in_sizes[0] / 128;
    const int E = in_sizes[1] / 2;
    const int* src = ei;
    const int* dst = ei + E;

    __half* bufH; float* bufF;
    cudaGetSymbolAddress((void**)&bufH, g_bufH);
    cudaGetSymbolAddress((void**)&bufF, g_bufF);

    const size_t smG128 = (size_t)(128 * 136) * 4;  // 69,632 B
    const size_t smG64  = (size_t)(128 * 72) * 4;   // 36,864 B
    cudaFuncSetAttribute(k_mmagemm<128, false>,
                         cudaFuncAttributeMaxDynamicSharedMemorySize, (int)smG128);
    cudaFuncSetAttribute(k_mmagemm<128, true>,
                         cudaFuncAttributeMaxDynamicSharedMemorySize, (int)smG128);
    cudaFuncSetAttribute(k_mmagemm<64, true>,
                         cudaFuncAttributeMaxDynamicSharedMemorySize, (int)smG64);

    const int TB = 256;
    const int gN  = (n + TB - 1) / TB;
    const int gE  = (E + TB - 1) / TB;
    const int gM  = (n + 127) / 128;
    const int gAg = (n * 32 + TB - 1) / TB;
    const int nch = (n + 1023) / 1024;

    // normalization + CSR build (shared by all 3 layers)
    k_deg_init<<<gN, TB>>>(n);
    k_deg_count<<<gE, TB>>>(dst, E);
    k_dis<<<gN, TB>>>(n);
    k_scan_chunk<<<nch, 1024>>>(n);
    k_scan_top<<<1, 128>>>(nch);
    k_scan_add<<<gN, TB>>>(n);
    k_csr_fill<<<gE, TB>>>(src, dst, E);

    // layer 1
    k_mmagemm<128, false><<<gM, TB, smG128>>>(x, W1, bufH, n);
    k_aggr<128><<<gAg, TB>>>(bufH, b1, bufF, n);

    // layer 2
    k_mmagemm<128, true><<<gM, TB, smG128>>>(bufF, W2, bufH, n);
    k_aggr<128><<<gAg, TB>>>(bufH, b2, bufF, n);

    // layer 3
    k_mmagemm<64, true><<<gM, TB, smG64>>>(bufF, W3, bufH, n);
    k_aggr<64><<<gAg, TB>>>(bufH, b3, out, n);
}

// round 11
// speedup vs baseline: 3.1875x; 1.1772x over previous
#include <cuda_runtime.h>
#include <cuda_fp16.h>
#include <cstdint>

constexpr int MAXN = 100000;
constexpr int MAXE = 1600000;
constexpr int C128 = 128;

// Scratch (__device__ globals; allocation-free rule)
__device__ __half g_bufH[(size_t)MAXN * C128];  // GEMM output (fp16 messages)
__device__ __half g_bufG[(size_t)MAXN * C128];  // aggr output (fp16 activations)
__device__ float  g_dis[MAXN];                  // deg^{-1/2}
__device__ int    g_deg[MAXN];                  // 1 + in-degree
__device__ int    g_rowoff[MAXN];               // CSR exclusive offsets
__device__ int    g_cur[MAXN];                  // fill cursors
__device__ int    g_chunksum[128];
__device__ int    g_chunkoff[128];
__device__ int2   g_csr[MAXE];                  // {src, norm bits}

// ---------------------------------------------------------------------------
// helpers
// ---------------------------------------------------------------------------
__device__ __forceinline__ void mma_f16(float* c, const uint32_t* a,
                                        const uint32_t* b) {
    asm volatile(
        "mma.sync.aligned.m16n8k16.row.col.f32.f16.f16.f32 "
        "{%0,%1,%2,%3}, {%4,%5,%6,%7}, {%8,%9}, {%0,%1,%2,%3};"
        : "+f"(c[0]), "+f"(c[1]), "+f"(c[2]), "+f"(c[3])
        : "r"(a[0]), "r"(a[1]), "r"(a[2]), "r"(a[3]), "r"(b[0]), "r"(b[1]));
}

// ---------------------------------------------------------------------------
// degree / norm
// ---------------------------------------------------------------------------
__global__ void k_deg_init(int n) {
    int i = blockIdx.x * blockDim.x + threadIdx.x;
    if (i < n) g_deg[i] = 1;
}
__global__ void k_deg_count(const int* __restrict__ dst, int e) {
    int i = blockIdx.x * blockDim.x + threadIdx.x;
    if (i < e) atomicAdd(&g_deg[dst[i]], 1);
}
__global__ void k_dis(int n) {
    int i = blockIdx.x * blockDim.x + threadIdx.x;
    if (i < n) g_dis[i] = rsqrtf((float)g_deg[i]);
}

// ---------------------------------------------------------------------------
// 2-level exclusive scan
// ---------------------------------------------------------------------------
__global__ __launch_bounds__(1024) void k_scan_chunk(int n) {
    __shared__ int sm[1024];
    int gid = blockIdx.x * 1024 + threadIdx.x;
    int v = (gid < n) ? (g_deg[gid] - 1) : 0;
    sm[threadIdx.x] = v;
    __syncthreads();
#pragma unroll
    for (int off = 1; off < 1024; off <<= 1) {
        int t = (threadIdx.x >= off) ? sm[threadIdx.x - off] : 0;
        __syncthreads();
        sm[threadIdx.x] += t;
        __syncthreads();
    }
    if (gid < n) g_rowoff[gid] = sm[threadIdx.x] - v;
    if (threadIdx.x == 1023) g_chunksum[blockIdx.x] = sm[1023];
}
__global__ void k_scan_top(int nch) {
    __shared__ int sm[128];
    int v = (threadIdx.x < nch) ? g_chunksum[threadIdx.x] : 0;
    sm[threadIdx.x] = v;
    __syncthreads();
#pragma unroll
    for (int off = 1; off < 128; off <<= 1) {
        int t = (threadIdx.x >= off) ? sm[threadIdx.x - off] : 0;
        __syncthreads();
        sm[threadIdx.x] += t;
        __syncthreads();
    }
    if (threadIdx.x < nch) g_chunkoff[threadIdx.x] = sm[threadIdx.x] - v;
}
__global__ void k_scan_add(int n) {
    int i = blockIdx.x * blockDim.x + threadIdx.x;
    if (i < n) {
        int o = g_rowoff[i] + g_chunkoff[i >> 10];
        g_rowoff[i] = o;
        g_cur[i] = o;
    }
}
__global__ void k_csr_fill(const int* __restrict__ src,
                           const int* __restrict__ dst, int E) {
    int e = blockIdx.x * blockDim.x + threadIdx.x;
    if (e < E) {
        int s = src[e], d = dst[e];
        int pos = atomicAdd(&g_cur[d], 1);
        float nrm = g_dis[s] * g_dis[d];
        g_csr[pos] = make_int2(s, __float_as_int(nrm));
    }
}

// ---------------------------------------------------------------------------
// fp16 tensor-core GEMM (mma.m16n8k16):
//   h16[n, COUT] = fp16( A[n,128] @ W[128, COUT] ), A fp32 or fp16.
// CTA 256 thr, M-tile 128, warps 4(M) x 2(N). B (W as fp16, [n][k] layout,
// stride 136 halves) in SMEM; fragment reads conflict-free. A fragments
// direct from global (u32 of 2 halves / float2+cvt for fp32 input).
// ---------------------------------------------------------------------------
template <int COUT, bool AHALF>
__global__ __launch_bounds__(256, 2) void k_mmagemm(const void* __restrict__ ain,
                                                    const float* __restrict__ W,
                                                    __half* __restrict__ h, int n) {
    constexpr int KS2 = 136;        // B row stride (halves)
    constexpr int WN = COUT / 2;    // warp N-tile
    constexpr int NI = WN / 8;      // n8 sub-tiles

    extern __shared__ __half Bs[];  // [COUT][KS2]

    const int tid = threadIdx.x;
    const int wid = tid >> 5;
    const int lane = tid & 31;
    const int m0 = blockIdx.x * 128;

    // --- Stage B: W[k][nc] fp32 -> Bs[nc][k] fp16 (coalesced reads) ---
    for (int idx = tid; idx < 128 * COUT; idx += 256) {
        int nc = idx % COUT, k = idx / COUT;
        Bs[nc * KS2 + k] = __float2half_rn(W[idx]);
    }
    __syncthreads();

    const int wm = wid & 3;
    const int wn = wid >> 2;
    const int rq = lane >> 2;       // 0..7
    const int qk = lane & 3;        // 0..3
    const int k0h0 = qk * 2;        // base half-offset within k16

    const int r_base = m0 + wm * 32 + rq;
    const bool v00 = (r_base      < n), v01 = (r_base + 8  < n);
    const bool v10 = (r_base + 16 < n), v11 = (r_base + 24 < n);

    const __half* ah = (const __half*)ain;
    const float*  af = (const float*)ain;

    float acc[2][NI][4];
#pragma unroll
    for (int mi = 0; mi < 2; mi++)
#pragma unroll
        for (int ni = 0; ni < NI; ni++)
#pragma unroll
            for (int j = 0; j < 4; j++) acc[mi][ni][j] = 0.f;

#pragma unroll
    for (int ks = 0; ks < 8; ks++) {
        const int kh = ks * 16 + k0h0;
        uint32_t a[2][4];
#pragma unroll
        for (int mi = 0; mi < 2; mi++) {
            const int r = r_base + mi * 16;
            const bool vlo = mi ? v10 : v00;
            const bool vhi = mi ? v11 : v01;
            if (AHALF) {
                a[mi][0] = vlo ? *(const uint32_t*)(ah + (size_t)r * 128 + kh) : 0u;
                a[mi][1] = vhi ? *(const uint32_t*)(ah + (size_t)(r + 8) * 128 + kh) : 0u;
                a[mi][2] = vlo ? *(const uint32_t*)(ah + (size_t)r * 128 + kh + 8) : 0u;
                a[mi][3] = vhi ? *(const uint32_t*)(ah + (size_t)(r + 8) * 128 + kh + 8) : 0u;
            } else {
                float2 f0 = vlo ? *(const float2*)(af + (size_t)r * 128 + kh)
                                : make_float2(0.f, 0.f);
                float2 f1 = vhi ? *(const float2*)(af + (size_t)(r + 8) * 128 + kh)
                                : make_float2(0.f, 0.f);
                float2 f2 = vlo ? *(const float2*)(af + (size_t)r * 128 + kh + 8)
                                : make_float2(0.f, 0.f);
                float2 f3 = vhi ? *(const float2*)(af + (size_t)(r + 8) * 128 + kh + 8)
                                : make_float2(0.f, 0.f);
                __half2 h0 = __floats2half2_rn(f0.x, f0.y);
                __half2 h1 = __floats2half2_rn(f1.x, f1.y);
                __half2 h2v = __floats2half2_rn(f2.x, f2.y);
                __half2 h3 = __floats2half2_rn(f3.x, f3.y);
                a[mi][0] = *(uint32_t*)&h0; a[mi][1] = *(uint32_t*)&h1;
                a[mi][2] = *(uint32_t*)&h2v; a[mi][3] = *(uint32_t*)&h3;
            }
        }
        uint32_t b[NI][2];
#pragma unroll
        for (int ni = 0; ni < NI; ni++) {
            int ncol = wn * WN + ni * 8 + rq;
            const __half* bp = Bs + ncol * KS2 + ks * 16 + k0h0;
            b[ni][0] = *(const uint32_t*)bp;
            b[ni][1] = *(const uint32_t*)(bp + 8);
        }
#pragma unroll
        for (int mi = 0; mi < 2; mi++)
#pragma unroll
            for (int ni = 0; ni < NI; ni++)
                mma_f16(acc[mi][ni], a[mi], b[ni]);
    }

    // --- Epilogue: packed half2 stores ---
    __half2* h2 = (__half2*)h;
#pragma unroll
    for (int mi = 0; mi < 2; mi++) {
        int r_lo = m0 + wm * 32 + mi * 16 + rq;
        int r_hi = r_lo + 8;
#pragma unroll
        for (int ni = 0; ni < NI; ni++) {
            int col = wn * WN + ni * 8 + qk * 2;
            if (r_lo < n)
                h2[(size_t)r_lo * (COUT / 2) + col / 2] =
                    __floats2half2_rn(acc[mi][ni][0], acc[mi][ni][1]);
            if (r_hi < n)
                h2[(size_t)r_hi * (COUT / 2) + col / 2] =
                    __floats2half2_rn(acc[mi][ni][2], acc[mi][ni][3]);
        }
    }
}

// ---------------------------------------------------------------------------
// CSR gather-aggregate, C=128, fp16 messages -> fp32 acc -> relu -> fp16 out
// ---------------------------------------------------------------------------
__global__ __launch_bounds__(256) void k_aggr_h(const __half* __restrict__ h,
                                                const float* __restrict__ b,
                                                __half* __restrict__ out, int n) {
    int i = (blockIdx.x * 256 + threadIdx.x) >> 5;
    int lane = threadIdx.x & 31;
    if (i >= n) return;

    float d = g_dis[i];
    float s2 = d * d;
    int e = g_rowoff[i];
    const int end = e + (g_deg[i] - 1);

    const uint2* h4 = (const uint2*)h;
    float4 acc = ((const float4*)b)[lane];
    {
        uint2 u = h4[(size_t)i * 32 + lane];
        float2 p0 = __half22float2(*(const __half2*)&u.x);
        float2 p1 = __half22float2(*(const __half2*)&u.y);
        acc.x = fmaf(s2, p0.x, acc.x); acc.y = fmaf(s2, p0.y, acc.y);
        acc.z = fmaf(s2, p1.x, acc.z); acc.w = fmaf(s2, p1.y, acc.w);
    }
    for (; e + 4 <= end; e += 4) {
        int2 e0 = __ldg(&g_csr[e]);
        int2 e1 = __ldg(&g_csr[e + 1]);
        int2 e2 = __ldg(&g_csr[e + 2]);
        int2 e3 = __ldg(&g_csr[e + 3]);
        uint2 u0 = h4[(size_t)e0.x * 32 + lane];
        uint2 u1 = h4[(size_t)e1.x * 32 + lane];
        uint2 u2 = h4[(size_t)e2.x * 32 + lane];
        uint2 u3 = h4[(size_t)e3.x * 32 + lane];
        float nr; float2 p0, p1;
        nr = __int_as_float(e0.y);
        p0 = __half22float2(*(const __half2*)&u0.x);
        p1 = __half22float2(*(const __half2*)&u0.y);
        acc.x = fmaf(nr, p0.x, acc.x); acc.y = fmaf(nr, p0.y, acc.y);
        acc.z = fmaf(nr, p1.x, acc.z); acc.w = fmaf(nr, p1.y, acc.w);
        nr = __int_as_float(e1.y);
        p0 = __half22float2(*(const __half2*)&u1.x);
        p1 = __half22float2(*(const __half2*)&u1.y);
        acc.x = fmaf(nr, p0.x, acc.x); acc.y = fmaf(nr, p0.y, acc.y);
        acc.z = fmaf(nr, p1.x, acc.z); acc.w = fmaf(nr, p1.y, acc.w);
        nr = __int_as_float(e2.y);
        p0 = __half22float2(*(const __half2*)&u2.x);
        p1 = __half22float2(*(const __half2*)&u2.y);
        acc.x = fmaf(nr, p0.x, acc.x); acc.y = fmaf(nr, p0.y, acc.y);
        acc.z = fmaf(nr, p1.x, acc.z); acc.w = fmaf(nr, p1.y, acc.w);
        nr = __int_as_float(e3.y);
        p0 = __half22float2(*(const __half2*)&u3.x);
        p1 = __half22float2(*(const __half2*)&u3.y);
        acc.x = fmaf(nr, p0.x, acc.x); acc.y = fmaf(nr, p0.y, acc.y);
        acc.z = fmaf(nr, p1.x, acc.z); acc.w = fmaf(nr, p1.y, acc.w);
    }
    for (; e < end; e++) {
        int2 ed = __ldg(&g_csr[e]);
        float nr = __int_as_float(ed.y);
        uint2 u = h4[(size_t)ed.x * 32 + lane];
        float2 p0 = __half22float2(*(const __half2*)&u.x);
        float2 p1 = __half22float2(*(const __half2*)&u.y);
        acc.x = fmaf(nr, p0.x, acc.x); acc.y = fmaf(nr, p0.y, acc.y);
        acc.z = fmaf(nr, p1.x, acc.z); acc.w = fmaf(nr, p1.y, acc.w);
    }
    // relu + fp16 pack
    __half2 o0 = __floats2half2_rn(fmaxf(acc.x, 0.f), fmaxf(acc.y, 0.f));
    __half2 o1 = __floats2half2_rn(fmaxf(acc.z, 0.f), fmaxf(acc.w, 0.f));
    uint2 o;
    o.x = *(uint32_t*)&o0; o.y = *(uint32_t*)&o1;
    ((uint2*)out)[(size_t)i * 32 + lane] = o;
}

// ---------------------------------------------------------------------------
// CSR gather-aggregate, C=64, fp16 messages -> fp32 out (final layer, no relu)
// ---------------------------------------------------------------------------
__global__ __launch_bounds__(256) void k_aggr_f(const __half* __restrict__ h,
                                                const float* __restrict__ b,
                                                float* __restrict__ out, int n) {
    int i = (blockIdx.x * 256 + threadIdx.x) >> 5;
    int lane = threadIdx.x & 31;
    if (i >= n) return;

    float d = g_dis[i];
    float s2 = d * d;
    int e = g_rowoff[i];
    const int end = e + (g_deg[i] - 1);

    const uint32_t* h2 = (const uint32_t*)h;
    float2 acc = ((const float2*)b)[lane];
    {
        uint32_t u = h2[(size_t)i * 32 + lane];
        float2 p = __half22float2(*(const __half2*)&u);
        acc.x = fmaf(s2, p.x, acc.x); acc.y = fmaf(s2, p.y, acc.y);
    }
    for (; e + 4 <= end; e += 4) {
        int2 e0 = __ldg(&g_csr[e]);
        int2 e1 = __ldg(&g_csr[e + 1]);
        int2 e2 = __ldg(&g_csr[e + 2]);
        int2 e3 = __ldg(&g_csr[e + 3]);
        uint32_t u0 = h2[(size_t)e0.x * 32 + lane];
        uint32_t u1 = h2[(size_t)e1.x * 32 + lane];
        uint32_t u2 = h2[(size_t)e2.x * 32 + lane];
        uint32_t u3 = h2[(size_t)e3.x * 32 + lane];
        float nr; float2 p;
        nr = __int_as_float(e0.y);
        p = __half22float2(*(const __half2*)&u0);
        acc.x = fmaf(nr, p.x, acc.x); acc.y = fmaf(nr, p.y, acc.y);
        nr = __int_as_float(e1.y);
        p = __half22float2(*(const __half2*)&u1);
        acc.x = fmaf(nr, p.x, acc.x); acc.y = fmaf(nr, p.y, acc.y);
        nr = __int_as_float(e2.y);
        p = __half22float2(*(const __half2*)&u2);
        acc.x = fmaf(nr, p.x, acc.x); acc.y = fmaf(nr, p.y, acc.y);
        nr = __int_as_float(e3.y);
        p = __half22float2(*(const __half2*)&u3);
        acc.x = fmaf(nr, p.x, acc.x); acc.y = fmaf(nr, p.y, acc.y);
    }
    for (; e < end; e++) {
        int2 ed = __ldg(&g_csr[e]);
        float nr = __int_as_float(ed.y);
        uint32_t u = h2[(size_t)ed.x * 32 + lane];
        float2 p = __half22float2(*(const __half2*)&u);
        acc.x = fmaf(nr, p.x, acc.x); acc.y = fmaf(nr, p.y, acc.y);
    }
    ((float2*)out)[(size_t)i * 32 + lane] = acc;
}

// ---------------------------------------------------------------------------
// Launch
// ---------------------------------------------------------------------------
extern "C" void kernel_launch(void* const* d_in, const int* in_sizes, int n_in,
                              void* d_out, int out_size) {
    const float* x  = (const float*)d_in[0];
    const int*   ei = (const int*)d_in[1];
    const float* W1 = (const float*)d_in[2];
    const float* b1 = (const float*)d_in[3];
    const float* W2 = (const float*)d_in[4];
    const float* b2 = (const float*)d_in[5];
    const float* W3 = (const float*)d_in[6];
    const float* b3 = (const float*)d_in[7];
    float* out = (float*)d_out;

    const int n = in_sizes[0] / 128;
    const int E = in_sizes[1] / 2;
    const int* src = ei;
    const int* dst = ei + E;

    __half* bufH; __half* bufG;
    cudaGetSymbolAddress((void**)&bufH, g_bufH);
    cudaGetSymbolAddress((void**)&bufG, g_bufG);

    const size_t smG128 = (size_t)128 * 136 * 2;  // 34,816 B
    const size_t smG64  = (size_t)64 * 136 * 2;   // 17,408 B
    cudaFuncSetAttribute(k_mmagemm<128, false>,
                         cudaFuncAttributeMaxDynamicSharedMemorySize, (int)smG128);
    cudaFuncSetAttribute(k_mmagemm<128, true>,
                         cudaFuncAttributeMaxDynamicSharedMemorySize, (int)smG128);
    cudaFuncSetAttribute(k_mmagemm<64, true>,
                         cudaFuncAttributeMaxDynamicSharedMemorySize, (int)smG64);

    const int TB = 256;
    const int gN  = (n + TB - 1) / TB;
    const int gE  = (E + TB - 1) / TB;
    const int gM  = (n + 127) / 128;
    const int gAg = (n * 32 + TB - 1) / TB;
    const int nch = (n + 1023) / 1024;

    // normalization + CSR build (shared by all 3 layers)
    k_deg_init<<<gN, TB>>>(n);
    k_deg_count<<<gE, TB>>>(dst, E);
    k_dis<<<gN, TB>>>(n);
    k_scan_chunk<<<nch, 1024>>>(n);
    k_scan_top<<<1, 128>>>(nch);
    k_scan_add<<<gN, TB>>>(n);
    k_csr_fill<<<gE, TB>>>(src, dst, E);

    // layer 1: h = x@W1 ; g = relu(aggr(h)+b1) (fp16)
    k_mmagemm<128, false><<<gM, TB, smG128>>>(x, W1, bufH, n);
    k_aggr_h<<<gAg, TB>>>(bufH, b1, bufG, n);

    // layer 2
    k_mmagemm<128, true><<<gM, TB, smG128>>>(bufG, W2, bufH, n);
    k_aggr_h<<<gAg, TB>>>(bufH, b2, bufG, n);

    // layer 3: final output fp32, no relu
    k_mmagemm<64, true><<<gM, TB, smG64>>>(bufG, W3, bufH, n);
    k_aggr_f<<<gAg, TB>>>(bufH, b3, out, n);
}

// round 14
// speedup vs baseline: 3.3719x; 1.0578x over previous
#include <cuda_runtime.h>
#include <cuda_fp16.h>
#include <cstdint>

constexpr int MAXN = 100000;
constexpr int MAXE = 1600000;
constexpr int C128 = 128;

// Scratch (__device__ globals; allocation-free rule)
__device__ __half g_bufH[(size_t)MAXN * C128];  // GEMM output (fp16 messages)
__device__ __half g_bufG[(size_t)MAXN * C128];  // aggr output (fp16 activations)
__device__ float  g_dis[MAXN];                  // (deg+1)^{-1/2}
__device__ int    g_deg[MAXN];                  // in-degree (memset to 0)
__device__ int    g_rowoff[MAXN];               // CSR exclusive offsets
__device__ int    g_cur[MAXN];                  // fill cursors
__device__ int    g_chunksum[128];
__device__ int    g_chunkoff[128];
__device__ int2   g_csr[MAXE];                  // {src, norm bits}

// ---------------------------------------------------------------------------
// helpers
// ---------------------------------------------------------------------------
__device__ __forceinline__ void mma_f16(float* c, const uint32_t* a,
                                        const uint32_t* b) {
    asm volatile(
        "mma.sync.aligned.m16n8k16.row.col.f32.f16.f16.f32 "
        "{%0,%1,%2,%3}, {%4,%5,%6,%7}, {%8,%9}, {%0,%1,%2,%3};"
        : "+f"(c[0]), "+f"(c[1]), "+f"(c[2]), "+f"(c[3])
        : "r"(a[0]), "r"(a[1]), "r"(a[2]), "r"(a[3]), "r"(b[0]), "r"(b[1]));
}

// ---------------------------------------------------------------------------
// degree
// ---------------------------------------------------------------------------
__global__ void k_deg_count(const int* __restrict__ dst, int e) {
    int i = blockIdx.x * blockDim.x + threadIdx.x;
    if (i < e) atomicAdd(&g_deg[dst[i]], 1);
}

// ---------------------------------------------------------------------------
// 2-level exclusive scan over in-degree; also computes dis = rsqrt(deg+1)
// ---------------------------------------------------------------------------
__global__ __launch_bounds__(1024) void k_scan_chunk(int n) {
    __shared__ int sm[1024];
    int gid = blockIdx.x * 1024 + threadIdx.x;
    int v = (gid < n) ? g_deg[gid] : 0;
    if (gid < n) g_dis[gid] = rsqrtf((float)(v + 1));
    sm[threadIdx.x] = v;
    __syncthreads();
#pragma unroll
    for (int off = 1; off < 1024; off <<= 1) {
        int t = (threadIdx.x >= off) ? sm[threadIdx.x - off] : 0;
        __syncthreads();
        sm[threadIdx.x] += t;
        __syncthreads();
    }
    if (gid < n) g_rowoff[gid] = sm[threadIdx.x] - v;
    if (threadIdx.x == 1023) g_chunksum[blockIdx.x] = sm[1023];
}
__global__ void k_scan_top(int nch) {
    __shared__ int sm[128];
    int v = (threadIdx.x < nch) ? g_chunksum[threadIdx.x] : 0;
    sm[threadIdx.x] = v;
    __syncthreads();
#pragma unroll
    for (int off = 1; off < 128; off <<= 1) {
        int t = (threadIdx.x >= off) ? sm[threadIdx.x - off] : 0;
        __syncthreads();
        sm[threadIdx.x] += t;
        __syncthreads();
    }
    if (threadIdx.x < nch) g_chunkoff[threadIdx.x] = sm[threadIdx.x] - v;
}
__global__ void k_scan_add(int n) {
    int i = blockIdx.x * blockDim.x + threadIdx.x;
    if (i < n) {
        int o = g_rowoff[i] + g_chunkoff[i >> 10];
        g_rowoff[i] = o;
        g_cur[i] = o;
    }
}
__global__ void k_csr_fill(const int* __restrict__ src,
                           const int* __restrict__ dst, int E) {
    int e = blockIdx.x * blockDim.x + threadIdx.x;
    if (e < E) {
        int s = src[e], d = dst[e];
        int pos = atomicAdd(&g_cur[d], 1);
        float nrm = g_dis[s] * g_dis[d];
        g_csr[pos] = make_int2(s, __float_as_int(nrm));
    }
}

// ---------------------------------------------------------------------------
// fp16 tensor-core GEMM (mma.m16n8k16):
//   h16[n, COUT] = fp16( A[n,128] @ W[128, COUT] ), A fp32 or fp16.
// ---------------------------------------------------------------------------
template <int COUT, bool AHALF>
__global__ __launch_bounds__(256, 2) void k_mmagemm(const void* __restrict__ ain,
                                                    const float* __restrict__ W,
                                                    __half* __restrict__ h, int n) {
    constexpr int KS2 = 136;        // B row stride (halves)
    constexpr int WN = COUT / 2;    // warp N-tile
    constexpr int NI = WN / 8;      // n8 sub-tiles

    extern __shared__ __half Bs[];  // [COUT][KS2]

    const int tid = threadIdx.x;
    const int wid = tid >> 5;
    const int lane = tid & 31;
    const int m0 = blockIdx.x * 128;

    // --- Stage B: W[k][nc] fp32 -> Bs[nc][k] fp16 ---
    for (int idx = tid; idx < 128 * COUT; idx += 256) {
        int nc = idx % COUT, k = idx / COUT;
        Bs[nc * KS2 + k] = __float2half_rn(W[idx]);
    }
    __syncthreads();

    const int wm = wid & 3;
    const int wn = wid >> 2;
    const int rq = lane >> 2;
    const int qk = lane & 3;
    const int k0h0 = qk * 2;

    const int r_base = m0 + wm * 32 + rq;
    const bool v00 = (r_base      < n), v01 = (r_base + 8  < n);
    const bool v10 = (r_base + 16 < n), v11 = (r_base + 24 < n);

    const __half* ah = (const __half*)ain;
    const float*  af = (const float*)ain;

    float acc[2][NI][4];
#pragma unroll
    for (int mi = 0; mi < 2; mi++)
#pragma unroll
        for (int ni = 0; ni < NI; ni++)
#pragma unroll
            for (int j = 0; j < 4; j++) acc[mi][ni][j] = 0.f;

#pragma unroll
    for (int ks = 0; ks < 8; ks++) {
        const int kh = ks * 16 + k0h0;
        uint32_t a[2][4];
#pragma unroll
        for (int mi = 0; mi < 2; mi++) {
            const int r = r_base + mi * 16;
            const bool vlo = mi ? v10 : v00;
            const bool vhi = mi ? v11 : v01;
            if (AHALF) {
                a[mi][0] = vlo ? *(const uint32_t*)(ah + (size_t)r * 128 + kh) : 0u;
                a[mi][1] = vhi ? *(const uint32_t*)(ah + (size_t)(r + 8) * 128 + kh) : 0u;
                a[mi][2] = vlo ? *(const uint32_t*)(ah + (size_t)r * 128 + kh + 8) : 0u;
                a[mi][3] = vhi ? *(const uint32_t*)(ah + (size_t)(r + 8) * 128 + kh + 8) : 0u;
            } else {
                float2 f0 = vlo ? *(const float2*)(af + (size_t)r * 128 + kh)
                                : make_float2(0.f, 0.f);
                float2 f1 = vhi ? *(const float2*)(af + (size_t)(r + 8) * 128 + kh)
                                : make_float2(0.f, 0.f);
                float2 f2 = vlo ? *(const float2*)(af + (size_t)r * 128 + kh + 8)
                                : make_float2(0.f, 0.f);
                float2 f3 = vhi ? *(const float2*)(af + (size_t)(r + 8) * 128 + kh + 8)
                                : make_float2(0.f, 0.f);
                __half2 h0 = __floats2half2_rn(f0.x, f0.y);
                __half2 h1 = __floats2half2_rn(f1.x, f1.y);
                __half2 h2v = __floats2half2_rn(f2.x, f2.y);
                __half2 h3 = __floats2half2_rn(f3.x, f3.y);
                a[mi][0] = *(uint32_t*)&h0; a[mi][1] = *(uint32_t*)&h1;
                a[mi][2] = *(uint32_t*)&h2v; a[mi][3] = *(uint32_t*)&h3;
            }
        }
        uint32_t b[NI][2];
#pragma unroll
        for (int ni = 0; ni < NI; ni++) {
            int ncol = wn * WN + ni * 8 + rq;
            const __half* bp = Bs + ncol * KS2 + ks * 16 + k0h0;
            b[ni][0] = *(const uint32_t*)bp;
            b[ni][1] = *(const uint32_t*)(bp + 8);
        }
#pragma unroll
        for (int mi = 0; mi < 2; mi++)
#pragma unroll
            for (int ni = 0; ni < NI; ni++)
                mma_f16(acc[mi][ni], a[mi], b[ni]);
    }

    __half2* h2 = (__half2*)h;
#pragma unroll
    for (int mi = 0; mi < 2; mi++) {
        int r_lo = m0 + wm * 32 + mi * 16 + rq;
        int r_hi = r_lo + 8;
#pragma unroll
        for (int ni = 0; ni < NI; ni++) {
            int col = wn * WN + ni * 8 + qk * 2;
            if (r_lo < n)
                h2[(size_t)r_lo * (COUT / 2) + col / 2] =
                    __floats2half2_rn(acc[mi][ni][0], acc[mi][ni][1]);
            if (r_hi < n)
                h2[(size_t)r_hi * (COUT / 2) + col / 2] =
                    __floats2half2_rn(acc[mi][ni][2], acc[mi][ni][3]);
        }
    }
}

// ---------------------------------------------------------------------------
// CSR gather-aggregate, C=128, fp16 messages -> fp32 acc -> relu -> fp16 out
// ---------------------------------------------------------------------------
__global__ __launch_bounds__(256) void k_aggr_h(const __half* __restrict__ h,
                                                const float* __restrict__ b,
                                                __half* __restrict__ out, int n) {
    int i = (blockIdx.x * 256 + threadIdx.x) >> 5;
    int lane = threadIdx.x & 31;
    if (i >= n) return;

    float d = g_dis[i];
    float s2 = d * d;
    int e = g_rowoff[i];
    const int end = e + g_deg[i];

    const uint2* h4 = (const uint2*)h;
    float4 acc = ((const float4*)b)[lane];
    {
        uint2 u = h4[(size_t)i * 32 + lane];
        float2 p0 = __half22float2(*(const __half2*)&u.x);
        float2 p1 = __half22float2(*(const __half2*)&u.y);
        acc.x = fmaf(s2, p0.x, acc.x); acc.y = fmaf(s2, p0.y, acc.y);
        acc.z = fmaf(s2, p1.x, acc.z); acc.w = fmaf(s2, p1.y, acc.w);
    }
    for (; e + 4 <= end; e += 4) {
        int2 e0 = __ldg(&g_csr[e]);
        int2 e1 = __ldg(&g_csr[e + 1]);
        int2 e2 = __ldg(&g_csr[e + 2]);
        int2 e3 = __ldg(&g_csr[e + 3]);
        uint2 u0 = h4[(size_t)e0.x * 32 + lane];
        uint2 u1 = h4[(size_t)e1.x * 32 + lane];
        uint2 u2 = h4[(size_t)e2.x * 32 + lane];
        uint2 u3 = h4[(size_t)e3.x * 32 + lane];
        float nr; float2 p0, p1;
        nr = __int_as_float(e0.y);
        p0 = __half22float2(*(const __half2*)&u0.x);
        p1 = __half22float2(*(const __half2*)&u0.y);
        acc.x = fmaf(nr, p0.x, acc.x); acc.y = fmaf(nr, p0.y, acc.y);
        acc.z = fmaf(nr, p1.x, acc.z); acc.w = fmaf(nr, p1.y, acc.w);
        nr = __int_as_float(e1.y);
        p0 = __half22float2(*(const __half2*)&u1.x);
        p1 = __half22float2(*(const __half2*)&u1.y);
        acc.x = fmaf(nr, p0.x, acc.x); acc.y = fmaf(nr, p0.y, acc.y);
        acc.z = fmaf(nr, p1.x, acc.z); acc.w = fmaf(nr, p1.y, acc.w);
        nr = __int_as_float(e2.y);
        p0 = __half22float2(*(const __half2*)&u2.x);
        p1 = __half22float2(*(const __half2*)&u2.y);
        acc.x = fmaf(nr, p0.x, acc.x); acc.y = fmaf(nr, p0.y, acc.y);
        acc.z = fmaf(nr, p1.x, acc.z); acc.w = fmaf(nr, p1.y, acc.w);
        nr = __int_as_float(e3.y);
        p0 = __half22float2(*(const __half2*)&u3.x);
        p1 = __half22float2(*(const __half2*)&u3.y);
        acc.x = fmaf(nr, p0.x, acc.x); acc.y = fmaf(nr, p0.y, acc.y);
        acc.z = fmaf(nr, p1.x, acc.z); acc.w = fmaf(nr, p1.y, acc.w);
    }
    for (; e < end; e++) {
        int2 ed = __ldg(&g_csr[e]);
        float nr = __int_as_float(ed.y);
        uint2 u = h4[(size_t)ed.x * 32 + lane];
        float2 p0 = __half22float2(*(const __half2*)&u.x);
        float2 p1 = __half22float2(*(const __half2*)&u.y);
        acc.x = fmaf(nr, p0.x, acc.x); acc.y = fmaf(nr, p0.y, acc.y);
        acc.z = fmaf(nr, p1.x, acc.z); acc.w = fmaf(nr, p1.y, acc.w);
    }
    __half2 o0 = __floats2half2_rn(fmaxf(acc.x, 0.f), fmaxf(acc.y, 0.f));
    __half2 o1 = __floats2half2_rn(fmaxf(acc.z, 0.f), fmaxf(acc.w, 0.f));
    uint2 o;
    o.x = *(uint32_t*)&o0; o.y = *(uint32_t*)&o1;
    ((uint2*)out)[(size_t)i * 32 + lane] = o;
}

// ---------------------------------------------------------------------------
// CSR gather-aggregate, C=64, fp16 messages -> fp32 out (final layer, no relu)
// ---------------------------------------------------------------------------
__global__ __launch_bounds__(256) void k_aggr_f(const __half* __restrict__ h,
                                                const float* __restrict__ b,
                                                float* __restrict__ out, int n) {
    int i = (blockIdx.x * 256 + threadIdx.x) >> 5;
    int lane = threadIdx.x & 31;
    if (i >= n) return;

    float d = g_dis[i];
    float s2 = d * d;
    int e = g_rowoff[i];
    const int end = e + g_deg[i];

    const uint32_t* h2 = (const uint32_t*)h;
    float2 acc = ((const float2*)b)[lane];
    {
        uint32_t u = h2[(size_t)i * 32 + lane];
        float2 p = __half22float2(*(const __half2*)&u);
        acc.x = fmaf(s2, p.x, acc.x); acc.y = fmaf(s2, p.y, acc.y);
    }
    for (; e + 4 <= end; e += 4) {
        int2 e0 = __ldg(&g_csr[e]);
        int2 e1 = __ldg(&g_csr[e + 1]);
        int2 e2 = __ldg(&g_csr[e + 2]);
        int2 e3 = __ldg(&g_csr[e + 3]);
        uint32_t u0 = h2[(size_t)e0.x * 32 + lane];
        uint32_t u1 = h2[(size_t)e1.x * 32 + lane];
        uint32_t u2 = h2[(size_t)e2.x * 32 + lane];
        uint32_t u3 = h2[(size_t)e3.x * 32 + lane];
        float nr; float2 p;
        nr = __int_as_float(e0.y);
        p = __half22float2(*(const __half2*)&u0);
        acc.x = fmaf(nr, p.x, acc.x); acc.y = fmaf(nr, p.y, acc.y);
        nr = __int_as_float(e1.y);
        p = __half22float2(*(const __half2*)&u1);
        acc.x = fmaf(nr, p.x, acc.x); acc.y = fmaf(nr, p.y, acc.y);
        nr = __int_as_float(e2.y);
        p = __half22float2(*(const __half2*)&u2);
        acc.x = fmaf(nr, p.x, acc.x); acc.y = fmaf(nr, p.y, acc.y);
        nr = __int_as_float(e3.y);
        p = __half22float2(*(const __half2*)&u3);
        acc.x = fmaf(nr, p.x, acc.x); acc.y = fmaf(nr, p.y, acc.y);
    }
    for (; e < end; e++) {
        int2 ed = __ldg(&g_csr[e]);
        float nr = __int_as_float(ed.y);
        uint32_t u = h2[(size_t)ed.x * 32 + lane];
        float2 p = __half22float2(*(const __half2*)&u);
        acc.x = fmaf(nr, p.x, acc.x); acc.y = fmaf(nr, p.y, acc.y);
    }
    ((float2*)out)[(size_t)i * 32 + lane] = acc;
}

// ---------------------------------------------------------------------------
// Launch: CSR build forked onto a side stream, overlapped with GEMM1.
// Streams/events created per call and leaked (2 calls total; no device mem).
// ---------------------------------------------------------------------------
extern "C" void kernel_launch(void* const* d_in, const int* in_sizes, int n_in,
                              void* d_out, int out_size) {
    const float* x  = (const float*)d_in[0];
    const int*   ei = (const int*)d_in[1];
    const float* W1 = (const float*)d_in[2];
    const float* b1 = (const float*)d_in[3];
    const float* W2 = (const float*)d_in[4];
    const float* b2 = (const float*)d_in[5];
    const float* W3 = (const float*)d_in[6];
    const float* b3 = (const float*)d_in[7];
    float* out = (float*)d_out;

    const int n = in_sizes[0] / 128;
    const int E = in_sizes[1] / 2;
    const int* src = ei;
    const int* dst = ei + E;

    __half* bufH; __half* bufG; int* degPtr;
    cudaGetSymbolAddress((void**)&bufH, g_bufH);
    cudaGetSymbolAddress((void**)&bufG, g_bufG);
    cudaGetSymbolAddress((void**)&degPtr, g_deg);

    const size_t smG128 = (size_t)128 * 136 * 2;  // 34,816 B
    const size_t smG64  = (size_t)64 * 136 * 2;   // 17,408 B
    cudaFuncSetAttribute(k_mmagemm<128, false>,
                         cudaFuncAttributeMaxDynamicSharedMemorySize, (int)smG128);
    cudaFuncSetAttribute(k_mmagemm<128, true>,
                         cudaFuncAttributeMaxDynamicSharedMemorySize, (int)smG128);
    cudaFuncSetAttribute(k_mmagemm<64, true>,
                         cudaFuncAttributeMaxDynamicSharedMemorySize, (int)smG64);

    const int TB = 256;
    const int gN  = (n + TB - 1) / TB;
    const int gE  = (E + TB - 1) / TB;
    const int gM  = (n + 127) / 128;
    const int gAg = (n * 32 + TB - 1) / TB;
    const int nch = (n + 1023) / 1024;

    cudaStream_t s2;
    cudaEvent_t evFork, evJoin;
    cudaStreamCreateWithFlags(&s2, cudaStreamNonBlocking);
    cudaEventCreateWithFlags(&evFork, cudaEventDisableTiming);
    cudaEventCreateWithFlags(&evJoin, cudaEventDisableTiming);

    // fork: side stream joins the capture via event dependency
    cudaEventRecord(evFork, 0);
    cudaStreamWaitEvent(s2, evFork, 0);

    // --- CSR build on side stream ---
    cudaMemsetAsync(degPtr, 0, (size_t)n * sizeof(int), s2);
    k_deg_count<<<gE, TB, 0, s2>>>(dst, E);
    k_scan_chunk<<<nch, 1024, 0, s2>>>(n);
    k_scan_top<<<1, 128, 0, s2>>>(nch);
    k_scan_add<<<gN, TB, 0, s2>>>(n);
    k_csr_fill<<<gE, TB, 0, s2>>>(src, dst, E);
    cudaEventRecord(evJoin, s2);

    // --- GEMM1 concurrently on main stream ---
    k_mmagemm<128, false><<<gM, TB, smG128>>>(x, W1, bufH, n);

    // join: aggregation needs both GEMM1 and CSR
    cudaStreamWaitEvent(0, evJoin, 0);
    k_aggr_h<<<gAg, TB>>>(bufH, b1, bufG, n);

    // layer 2
    k_mmagemm<128, true><<<gM, TB, smG128>>>(bufG, W2, bufH, n);
    k_aggr_h<<<gAg, TB>>>(bufH, b2, bufG, n);

    // layer 3: final output fp32, no relu
    k_mmagemm<64, true><<<gM, TB, smG64>>>(bufG, W3, bufH, n);
    k_aggr_f<<<gAg, TB>>>(bufH, b3, out, n);
}